// round 12
// baseline (speedup 1.0000x reference)
#include <cuda_runtime.h>
#include <cuda_fp16.h>
#include <math.h>
#include <stdint.h>

// ---------------- problem constants ----------------
#define NB   16
#define NT   512
#define TOK  (NB*NT)        // 8192 tokens
#define HD   768
#define T3   (3*HD)         // 2304
#define DFF  3072
#define NHH  12
#define DH   64
#define NLB  9
#define NBH  (NB*NHH)       // 192
#define NLAY 4

// ---------------- scratch (static device globals; no runtime alloc) ----------------
__device__ float g_x[TOK*HD];
__device__ float g_y[TOK*HD];
__device__ float g_logits[TOK*NLB];
__device__ float g_llh[NB];

__device__ __half g_xh[TOK*HD],   g_xl[TOK*HD];
__device__ __half g_qkvh[TOK*T3], g_qkvl[TOK*T3];
__device__ __half g_ctxh[TOK*HD], g_ctxl[TOK*HD];
__device__ __half g_ffh[TOK*DFF], g_ffl[TOK*DFF];
__device__ __half g_wqh[NLAY*HD*T3],  g_wql[NLAY*HD*T3];
__device__ __half g_woh[NLAY*HD*HD],  g_wol[NLAY*HD*HD];
__device__ __half g_w1h[NLAY*HD*DFF], g_w1l[NLAY*HD*DFF];
__device__ __half g_w2h[NLAY*DFF*HD], g_w2l[NLAY*DFF*HD];

// ---------------- helpers ----------------
__device__ __forceinline__ uint32_t s2u(const void* p) {
    uint32_t a;
    asm("{ .reg .u64 t; cvta.to.shared.u64 t, %1; cvt.u32.u64 %0, t; }" : "=r"(a) : "l"(p));
    return a;
}
__device__ __forceinline__ void splitpack(float a, float b, uint32_t& H, uint32_t& L) {
    __half2 h = __floats2half2_rn(a, b);
    float2 hf = __half22float2(h);
    __half2 l = __floats2half2_rn(a - hf.x, b - hf.y);
    H = *(uint32_t*)&h;
    L = *(uint32_t*)&l;
}
__device__ __forceinline__ void ldmx4(uint32_t* r, uint32_t addr) {
    asm volatile("ldmatrix.sync.aligned.m8n8.x4.shared.b16 {%0,%1,%2,%3}, [%4];"
        : "=r"(r[0]), "=r"(r[1]), "=r"(r[2]), "=r"(r[3]) : "r"(addr));
}
__device__ __forceinline__ void ldmx2(uint32_t* r, uint32_t addr) {
    asm volatile("ldmatrix.sync.aligned.m8n8.x2.shared.b16 {%0,%1}, [%2];"
        : "=r"(r[0]), "=r"(r[1]) : "r"(addr));
}
__device__ __forceinline__ void ldmx2t(uint32_t* r, uint32_t addr) {
    asm volatile("ldmatrix.sync.aligned.m8n8.x2.trans.shared.b16 {%0,%1}, [%2];"
        : "=r"(r[0]), "=r"(r[1]) : "r"(addr));
}
__device__ __forceinline__ void mma16816(float* c, const uint32_t* a, const uint32_t* b) {
    asm volatile(
        "mma.sync.aligned.m16n8k16.row.col.f32.f16.f16.f32 "
        "{%0,%1,%2,%3}, {%4,%5,%6,%7}, {%8,%9}, {%0,%1,%2,%3};"
        : "+f"(c[0]), "+f"(c[1]), "+f"(c[2]), "+f"(c[3])
        : "r"(a[0]), "r"(a[1]), "r"(a[2]), "r"(a[3]), "r"(b[0]), "r"(b[1]));
}
__device__ __forceinline__ float gelu_tanh(float v) {
    float u = 0.7978845608028654f * (v + 0.044715f * v * v * v);
    return 0.5f * v * (1.f + tanhf(u));
}

// ---------------- fp32 -> split half (weights) ----------------
__global__ void __launch_bounds__(256) split_kernel(
    const float* __restrict__ s, __half* __restrict__ h, __half* __restrict__ l, int n)
{
    int i = (blockIdx.x * blockDim.x + threadIdx.x) * 4;
    if (i >= n) return;
    float4 v = *(const float4*)(s + i);
    uint32_t H0, L0, H1, L1;
    splitpack(v.x, v.y, H0, L0);
    splitpack(v.z, v.w, H1, L1);
    *(uint32_t*)(h + i) = H0; *(uint32_t*)(h + i + 2) = H1;
    *(uint32_t*)(l + i) = L0; *(uint32_t*)(l + i + 2) = L1;
}

// ================= 3xFP16 GEMM, double-buffered SMEM pipeline =================
// C = A @ B + bias.  EPI: 0 -> fp32 C; 1 -> half CH/CL + gelu; 2 -> half CH/CL.
// Stage layout (bytes): AH 0 (128x40h), AL 10240, BH 20480 (32x136h), BL 29184. Stage stride 37888.
#define G_STAGE 37888
#define GEMM_SMEM (2*G_STAGE)
template<int EPI>
__global__ void __launch_bounds__(256, 2) gemm_h(
    const __half* __restrict__ AH, const __half* __restrict__ AL,
    const __half* __restrict__ BH, const __half* __restrict__ BL,
    const float* __restrict__ bias,
    float* __restrict__ Cf, __half* __restrict__ CH, __half* __restrict__ CL,
    int M, int N, int K)
{
    extern __shared__ char smem[];
    uint32_t sb = s2u(smem);

    const int tid = threadIdx.x, warp = tid >> 5, lane = tid & 31;
    const int m0 = blockIdx.y * 128, n0 = blockIdx.x * 128;
    const int wm = (warp >> 2) * 64, wn = (warp & 3) * 32;
    const int g = lane >> 2, tg = lane & 3;

    const int am = tid >> 1, ac = (tid & 1) * 16;
    const int bk = tid >> 3, bn = (tid & 7) * 16;
    const __half* AHp = AH + (size_t)(m0 + am) * K + ac;
    const __half* ALp = AL + (size_t)(m0 + am) * K + ac;
    const __half* BHp = BH + n0 + bn;
    const __half* BLp = BL + n0 + bn;

    uint32_t aoff = (uint32_t)((wm + (lane & 15)) * 80 + (lane >> 4) * 16);
    uint32_t boff = (uint32_t)(((lane & 7) + 8 * ((lane >> 3) & 1)) * 272 + wn * 2);
    const uint32_t aW = (uint32_t)(am * 80 + ac * 2);
    const uint32_t bW = (uint32_t)(bk * 272 + bn * 2);

    uint4 rah[2], ral[2], rbh[2], rbl[2];
    rah[0] = *(const uint4*)(AHp);     rah[1] = *(const uint4*)(AHp + 8);
    ral[0] = *(const uint4*)(ALp);     ral[1] = *(const uint4*)(ALp + 8);
    rbh[0] = *(const uint4*)(BHp + (size_t)bk * N);
    rbh[1] = *(const uint4*)(BHp + (size_t)bk * N + 8);
    rbl[0] = *(const uint4*)(BLp + (size_t)bk * N);
    rbl[1] = *(const uint4*)(BLp + (size_t)bk * N + 8);

    float acc[16][4];
    #pragma unroll
    for (int i = 0; i < 16; i++) { acc[i][0] = acc[i][1] = acc[i][2] = acc[i][3] = 0.f; }

    // store stage 0
    {
        char* stp = smem;
        *(uint4*)(stp + aW) = rah[0];          *(uint4*)(stp + aW + 16) = rah[1];
        *(uint4*)(stp + 10240 + aW) = ral[0];  *(uint4*)(stp + 10240 + aW + 16) = ral[1];
        *(uint4*)(stp + 20480 + bW) = rbh[0];  *(uint4*)(stp + 20480 + bW + 16) = rbh[1];
        *(uint4*)(stp + 29184 + bW) = rbl[0];  *(uint4*)(stp + 29184 + bW + 16) = rbl[1];
    }
    __syncthreads();

    const int Tn = K >> 5;
    for (int t = 0; t < Tn; t++) {
        const int st = t & 1;
        if (t + 1 < Tn) {
            int k0 = (t + 1) << 5;
            rah[0] = *(const uint4*)(AHp + k0);     rah[1] = *(const uint4*)(AHp + k0 + 8);
            ral[0] = *(const uint4*)(ALp + k0);     ral[1] = *(const uint4*)(ALp + k0 + 8);
            rbh[0] = *(const uint4*)(BHp + (size_t)(k0 + bk) * N);
            rbh[1] = *(const uint4*)(BHp + (size_t)(k0 + bk) * N + 8);
            rbl[0] = *(const uint4*)(BLp + (size_t)(k0 + bk) * N);
            rbl[1] = *(const uint4*)(BLp + (size_t)(k0 + bk) * N + 8);
        }
        const uint32_t aHb = sb + st * G_STAGE;
        const uint32_t aLb = aHb + 10240;
        const uint32_t bHb = aHb + 20480;
        const uint32_t bLb = aHb + 29184;
        #pragma unroll
        for (int kk = 0; kk < 2; kk++) {
            uint32_t aHf[4][4], aLf[4][4], bHf[4][2], bLf[4][2];
            #pragma unroll
            for (int mf = 0; mf < 4; mf++) {
                ldmx4(aHf[mf], aHb + aoff + mf * 1280 + kk * 32);
                ldmx4(aLf[mf], aLb + aoff + mf * 1280 + kk * 32);
            }
            #pragma unroll
            for (int nf = 0; nf < 4; nf++) {
                ldmx2t(bHf[nf], bHb + boff + nf * 16 + kk * 4352);
                ldmx2t(bLf[nf], bLb + boff + nf * 16 + kk * 4352);
            }
            #pragma unroll
            for (int mf = 0; mf < 4; mf++)
                #pragma unroll
                for (int nf = 0; nf < 4; nf++) {
                    float* c = acc[mf * 4 + nf];
                    mma16816(c, aLf[mf], bHf[nf]);
                    mma16816(c, aHf[mf], bLf[nf]);
                    mma16816(c, aHf[mf], bHf[nf]);
                }
        }
        if (t + 1 < Tn) {
            char* stp = smem + (st ^ 1) * G_STAGE;
            *(uint4*)(stp + aW) = rah[0];          *(uint4*)(stp + aW + 16) = rah[1];
            *(uint4*)(stp + 10240 + aW) = ral[0];  *(uint4*)(stp + 10240 + aW + 16) = ral[1];
            *(uint4*)(stp + 20480 + bW) = rbh[0];  *(uint4*)(stp + 20480 + bW + 16) = rbh[1];
            *(uint4*)(stp + 29184 + bW) = rbl[0];  *(uint4*)(stp + 29184 + bW + 16) = rbl[1];
        }
        __syncthreads();
    }

    #pragma unroll
    for (int mf = 0; mf < 4; mf++)
        #pragma unroll
        for (int nf = 0; nf < 4; nf++) {
            const float* c = acc[mf * 4 + nf];
            int mrow = m0 + wm + mf * 16 + g;
            int ncol = n0 + wn + nf * 8 + tg * 2;
            float b0 = bias[ncol], b1 = bias[ncol + 1];
            float v0 = c[0] + b0, v1 = c[1] + b1, v2 = c[2] + b0, v3 = c[3] + b1;
            if (EPI == 1) { v0 = gelu_tanh(v0); v1 = gelu_tanh(v1); v2 = gelu_tanh(v2); v3 = gelu_tanh(v3); }
            if (EPI == 0) {
                Cf[(size_t)mrow * N + ncol]           = v0;
                Cf[(size_t)mrow * N + ncol + 1]       = v1;
                Cf[(size_t)(mrow + 8) * N + ncol]     = v2;
                Cf[(size_t)(mrow + 8) * N + ncol + 1] = v3;
            } else {
                uint32_t H, L;
                splitpack(v0, v1, H, L);
                *(uint32_t*)&CH[(size_t)mrow * N + ncol] = H;
                *(uint32_t*)&CL[(size_t)mrow * N + ncol] = L;
                splitpack(v2, v3, H, L);
                *(uint32_t*)&CH[(size_t)(mrow + 8) * N + ncol] = H;
                *(uint32_t*)&CL[(size_t)(mrow + 8) * N + ncol] = L;
            }
        }
}

// ================= fused flash attention (3xFP16 mma, online softmax) =================
// grid: (4 m-tiles, NBH). 256 threads, 8 warps x 16 query rows.
// Key tiles of 64, 8 iterations; next K/V tile prefetched into registers during mma.
#define ATTN_SMEM (73984)
__global__ void __launch_bounds__(256, 1) attn_fused(
    const __half* __restrict__ QKVH, const __half* __restrict__ QKVL,
    const int* __restrict__ amask,
    __half* __restrict__ CTXH, __half* __restrict__ CTXL)
{
    extern __shared__ char smraw[];
    __half* QsH = (__half*)smraw;          // [128][72]
    __half* QsL = QsH + 128 * 72;
    __half* KsH = QsL + 128 * 72;          // [64][72]
    __half* KsL = KsH + 64 * 72;
    __half* VsH = KsL + 64 * 72;           // [64][72]
    __half* VsL = VsH + 64 * 72;
    float*  mkf = (float*)(VsL + 64 * 72); // [64]

    const int tid = threadIdx.x, warp = tid >> 5, lane = tid & 31;
    const int bh = blockIdx.y, b = bh / NHH, h = bh % NHH;
    const int m0 = blockIdx.x * 128;
    const int g = lane >> 2, tg = lane & 3;

    // stage Q tile (pre-split halves straight from qkv)
    {
        int am = tid >> 1, ac = (tid & 1) * 32;
        const __half* qh = QKVH + (size_t)(b * NT + m0 + am) * T3 + h * DH + ac;
        const __half* ql = QKVL + (size_t)(b * NT + m0 + am) * T3 + h * DH + ac;
        #pragma unroll
        for (int i = 0; i < 4; i++) {
            *(uint4*)&QsH[am * 72 + ac + i * 8] = *(const uint4*)(qh + i * 8);
            *(uint4*)&QsL[am * 72 + ac + i * 8] = *(const uint4*)(ql + i * 8);
        }
    }
    __syncthreads();

    uint32_t qsHb = s2u(QsH), qsLb = s2u(QsL);
    uint32_t ksHb = s2u(KsH), ksLb = s2u(KsL);
    uint32_t vsHb = s2u(VsH), vsLb = s2u(VsL);
    uint32_t qoff = (uint32_t)((warp * 16 + (lane & 15)) * 144 + (lane >> 4) * 16);
    uint32_t koff = (uint32_t)((lane & 7) * 144 + ((lane >> 3) & 1) * 16);
    uint32_t voff = (uint32_t)(((lane & 7) + 8 * ((lane >> 3) & 1)) * 144);

    uint32_t qH[4][4], qL[4][4];
    #pragma unroll
    for (int kc = 0; kc < 4; kc++) {
        ldmx4(qH[kc], qsHb + qoff + kc * 32);
        ldmx4(qL[kc], qsLb + qoff + kc * 32);
    }

    float o[8][4];
    #pragma unroll
    for (int i = 0; i < 8; i++) { o[i][0] = o[i][1] = o[i][2] = o[i][3] = 0.f; }
    float mA = -1e30f, mB = -1e30f, lA = 0.f, lB = 0.f;

    const int krow = tid >> 2, kseg = (tid & 3) * 16;
    const __half* KHp = QKVH + (size_t)(b * NT + krow) * T3 + HD + h * DH + kseg;
    const __half* KLp = QKVL + (size_t)(b * NT + krow) * T3 + HD + h * DH + kseg;
    const __half* VHp = KHp + HD;
    const __half* VLp = KLp + HD;
    const size_t kstride = (size_t)64 * T3;

    // prefetch tile 0
    uint4 rk[2], rkl[2], rv[2], rvl[2];
    int pmask = 0;
    rk[0]  = *(const uint4*)(KHp);      rk[1]  = *(const uint4*)(KHp + 8);
    rkl[0] = *(const uint4*)(KLp);      rkl[1] = *(const uint4*)(KLp + 8);
    rv[0]  = *(const uint4*)(VHp);      rv[1]  = *(const uint4*)(VHp + 8);
    rvl[0] = *(const uint4*)(VLp);      rvl[1] = *(const uint4*)(VLp + 8);
    if (tid < 64) pmask = amask[b * NT + tid];

    for (int kt = 0; kt < 8; kt++) {
        // store prefetched tile
        *(uint4*)&KsH[krow * 72 + kseg]     = rk[0];
        *(uint4*)&KsH[krow * 72 + kseg + 8] = rk[1];
        *(uint4*)&KsL[krow * 72 + kseg]     = rkl[0];
        *(uint4*)&KsL[krow * 72 + kseg + 8] = rkl[1];
        *(uint4*)&VsH[krow * 72 + kseg]     = rv[0];
        *(uint4*)&VsH[krow * 72 + kseg + 8] = rv[1];
        *(uint4*)&VsL[krow * 72 + kseg]     = rvl[0];
        *(uint4*)&VsL[krow * 72 + kseg + 8] = rvl[1];
        if (tid < 64) mkf[tid] = (1.f - (float)pmask) * -1e9f;
        __syncthreads();

        // prefetch next tile (overlaps with mma below)
        if (kt + 1 < 8) {
            size_t off = (size_t)(kt + 1) * kstride;
            rk[0]  = *(const uint4*)(KHp + off);      rk[1]  = *(const uint4*)(KHp + off + 8);
            rkl[0] = *(const uint4*)(KLp + off);      rkl[1] = *(const uint4*)(KLp + off + 8);
            rv[0]  = *(const uint4*)(VHp + off);      rv[1]  = *(const uint4*)(VHp + off + 8);
            rvl[0] = *(const uint4*)(VLp + off);      rvl[1] = *(const uint4*)(VLp + off + 8);
            if (tid < 64) pmask = amask[b * NT + (kt + 1) * 64 + tid];
        }

        // S = Q @ K^T for this 16x64 warp tile
        float s[8][4];
        #pragma unroll
        for (int i = 0; i < 8; i++) { s[i][0] = s[i][1] = s[i][2] = s[i][3] = 0.f; }
        #pragma unroll
        for (int nf = 0; nf < 8; nf++) {
            #pragma unroll
            for (int kc = 0; kc < 4; kc++) {
                uint32_t bH[2], bL[2];
                ldmx2(bH, ksHb + koff + nf * 1152 + kc * 32);
                ldmx2(bL, ksLb + koff + nf * 1152 + kc * 32);
                mma16816(s[nf], qL[kc], bH);
                mma16816(s[nf], qH[kc], bL);
                mma16816(s[nf], qH[kc], bH);
            }
        }

        // scale + mask, row max
        float rmA = -1e30f, rmB = -1e30f;
        #pragma unroll
        for (int nf = 0; nf < 8; nf++) {
            float d0 = mkf[nf * 8 + tg * 2], d1 = mkf[nf * 8 + tg * 2 + 1];
            s[nf][0] = s[nf][0] * 0.125f + d0;
            s[nf][1] = s[nf][1] * 0.125f + d1;
            s[nf][2] = s[nf][2] * 0.125f + d0;
            s[nf][3] = s[nf][3] * 0.125f + d1;
            rmA = fmaxf(rmA, fmaxf(s[nf][0], s[nf][1]));
            rmB = fmaxf(rmB, fmaxf(s[nf][2], s[nf][3]));
        }
        rmA = fmaxf(rmA, __shfl_xor_sync(0xffffffffu, rmA, 1));
        rmA = fmaxf(rmA, __shfl_xor_sync(0xffffffffu, rmA, 2));
        rmB = fmaxf(rmB, __shfl_xor_sync(0xffffffffu, rmB, 1));
        rmB = fmaxf(rmB, __shfl_xor_sync(0xffffffffu, rmB, 2));

        float nmA = fmaxf(mA, rmA), nmB = fmaxf(mB, rmB);
        float cA = __expf(mA - nmA), cB = __expf(mB - nmB);
        float rsA = 0.f, rsB = 0.f;
        #pragma unroll
        for (int nf = 0; nf < 8; nf++) {
            s[nf][0] = __expf(s[nf][0] - nmA);
            s[nf][1] = __expf(s[nf][1] - nmA);
            s[nf][2] = __expf(s[nf][2] - nmB);
            s[nf][3] = __expf(s[nf][3] - nmB);
            rsA += s[nf][0] + s[nf][1];
            rsB += s[nf][2] + s[nf][3];
        }
        rsA += __shfl_xor_sync(0xffffffffu, rsA, 1);
        rsA += __shfl_xor_sync(0xffffffffu, rsA, 2);
        rsB += __shfl_xor_sync(0xffffffffu, rsB, 1);
        rsB += __shfl_xor_sync(0xffffffffu, rsB, 2);
        lA = lA * cA + rsA;
        lB = lB * cB + rsB;
        mA = nmA; mB = nmB;
        #pragma unroll
        for (int i = 0; i < 8; i++) {
            o[i][0] *= cA; o[i][1] *= cA;
            o[i][2] *= cB; o[i][3] *= cB;
        }

        // O += P @ V   (P from S fragments directly, split hi/lo)
        #pragma unroll
        for (int kc = 0; kc < 4; kc++) {
            uint32_t pH[4], pL[4];
            splitpack(s[2 * kc][0],     s[2 * kc][1],     pH[0], pL[0]);
            splitpack(s[2 * kc][2],     s[2 * kc][3],     pH[1], pL[1]);
            splitpack(s[2 * kc + 1][0], s[2 * kc + 1][1], pH[2], pL[2]);
            splitpack(s[2 * kc + 1][2], s[2 * kc + 1][3], pH[3], pL[3]);
            #pragma unroll
            for (int nf = 0; nf < 8; nf++) {
                uint32_t vH[2], vL[2];
                ldmx2t(vH, vsHb + voff + nf * 16 + kc * 2304);
                ldmx2t(vL, vsLb + voff + nf * 16 + kc * 2304);
                mma16816(o[nf], pL, vH);
                mma16816(o[nf], pH, vL);
                mma16816(o[nf], pH, vH);
            }
        }
        __syncthreads();   // tile fully consumed before next store
    }

    // epilogue: O / l, split to halves
    float iA = 1.f / lA, iB = 1.f / lB;
    int rowA = b * NT + m0 + warp * 16 + g;
    #pragma unroll
    for (int nf = 0; nf < 8; nf++) {
        int ncol = h * DH + nf * 8 + tg * 2;
        uint32_t H, L;
        splitpack(o[nf][0] * iA, o[nf][1] * iA, H, L);
        *(uint32_t*)&CTXH[(size_t)rowA * HD + ncol] = H;
        *(uint32_t*)&CTXL[(size_t)rowA * HD + ncol] = L;
        splitpack(o[nf][2] * iB, o[nf][3] * iB, H, L);
        *(uint32_t*)&CTXH[(size_t)(rowA + 8) * HD + ncol] = H;
        *(uint32_t*)&CTXL[(size_t)(rowA + 8) * HD + ncol] = L;
    }
}

// ---------------- reductions ----------------
__device__ __forceinline__ void reduce2_256(float& a, float& b) {
    __shared__ float sa[8], sb[8];
    #pragma unroll
    for (int o = 16; o; o >>= 1) {
        a += __shfl_xor_sync(0xffffffffu, a, o);
        b += __shfl_xor_sync(0xffffffffu, b, o);
    }
    int w = threadIdx.x >> 5;
    if ((threadIdx.x & 31) == 0) { sa[w] = a; sb[w] = b; }
    __syncthreads();
    a = 0.f; b = 0.f;
    #pragma unroll
    for (int i = 0; i < 8; i++) { a += sa[i]; b += sb[i]; }
}

// ---------------- embedding + LN ----------------
__global__ void __launch_bounds__(256) embed_ln_kernel(
    const int* __restrict__ ids, const int* __restrict__ tt,
    const float* __restrict__ we, const float* __restrict__ pe, const float* __restrict__ te,
    const float* __restrict__ sc, const float* __restrict__ bi,
    float* __restrict__ x, __half* __restrict__ xh, __half* __restrict__ xl)
{
    int tok = blockIdx.x;
    int t   = tok & (NT - 1);
    int tid = threadIdx.x;
    const float* w  = we + (size_t)ids[tok] * HD;
    const float* p  = pe + (size_t)t * HD;
    const float* ty = te + (size_t)tt[tok] * HD;
    float e[3]; float sum = 0.f, sq = 0.f;
    #pragma unroll
    for (int i = 0; i < 3; i++) {
        int c = tid + i * 256;
        float v = w[c] + p[c] + ty[c];
        e[i] = v; sum += v; sq += v * v;
    }
    reduce2_256(sum, sq);
    float mean = sum * (1.f / HD);
    float var  = sq * (1.f / HD) - mean * mean;
    float inv  = rsqrtf(var + 1e-12f);
    #pragma unroll
    for (int i = 0; i < 3; i++) {
        int c = tid + i * 256;
        float v = (e[i] - mean) * inv * sc[c] + bi[c];
        size_t idx = (size_t)tok * HD + c;
        x[idx] = v;
        __half h = __float2half_rn(v);
        xh[idx] = h;
        xl[idx] = __float2half_rn(v - __half2float(h));
    }
}

// ---------------- residual + LN ----------------
__global__ void __launch_bounds__(256) ln_res_kernel(
    const float* __restrict__ xin, const float* __restrict__ y,
    const float* __restrict__ sc, const float* __restrict__ bi,
    float* __restrict__ xout, __half* __restrict__ xh, __half* __restrict__ xl)
{
    int tok = blockIdx.x;
    int tid = threadIdx.x;
    float e[3]; float sum = 0.f, sq = 0.f;
    #pragma unroll
    for (int i = 0; i < 3; i++) {
        int c = tid + i * 256;
        float v = xin[(size_t)tok * HD + c] + y[(size_t)tok * HD + c];
        e[i] = v; sum += v; sq += v * v;
    }
    reduce2_256(sum, sq);
    float mean = sum * (1.f / HD);
    float var  = sq * (1.f / HD) - mean * mean;
    float inv  = rsqrtf(var + 1e-12f);
    #pragma unroll
    for (int i = 0; i < 3; i++) {
        int c = tid + i * 256;
        float v = (e[i] - mean) * inv * sc[c] + bi[c];
        size_t idx = (size_t)tok * HD + c;
        xout[idx] = v;
        __half h = __float2half_rn(v);
        xh[idx] = h;
        xl[idx] = __float2half_rn(v - __half2float(h));
    }
}

// ---------------- classifier ----------------
__global__ void __launch_bounds__(256) cls_kernel(
    const float* __restrict__ x, const float* __restrict__ W,
    const float* __restrict__ bias, float* __restrict__ out)
{
    int idx = blockIdx.x * blockDim.x + threadIdx.x;
    if (idx >= TOK * NLB) return;
    int tok = idx / NLB, n = idx % NLB;
    const float* xr = x + (size_t)tok * HD;
    float s = bias[n];
    #pragma unroll 8
    for (int k = 0; k < HD; k++) s = fmaf(xr[k], W[k * NLB + n], s);
    out[idx] = s;
}

// ---------------- CRF ----------------
__global__ void __launch_bounds__(128) crf_kernel(
    const float* __restrict__ logits, const int* __restrict__ labels,
    const int* __restrict__ amask, const float* __restrict__ startv,
    const float* __restrict__ endv, const float* __restrict__ trans,
    float* __restrict__ llh, float* __restrict__ dout)
{
    __shared__ float em[511 * NLB];
    __shared__ float tr[NLB * NLB];
    __shared__ unsigned char bp[510 * NLB];
    __shared__ float mk[511];
    __shared__ int   tg[511];
    __shared__ float sd[NLB], sv[NLB];

    int b = blockIdx.x, tid = threadIdx.x;
    const float* lp = logits + (size_t)(b * NT + 1) * NLB;
    for (int i = tid; i < 511 * NLB; i += blockDim.x) em[i] = lp[i];
    for (int i = tid; i < NLB * NLB; i += blockDim.x) tr[i] = trans[i];
    for (int i = tid; i < 511; i += blockDim.x) {
        mk[i] = (float)amask[b * NT + 1 + i];
        tg[i] = labels[b * NT + 1 + i];
    }
    __syncthreads();

    if (tid < 32) {
        int j = tid;
        float tc[NLB];
        if (j < NLB) {
            #pragma unroll
            for (int i = 0; i < NLB; i++) tc[i] = tr[i * NLB + j];
            sd[j] = startv[j] + em[j];
            sv[j] = sd[j];
        }
        __syncwarp();
        float num = 0.f; int prev = 0;
        if (j == 0) { prev = tg[0]; num = startv[prev] + em[prev]; }

        for (int s = 1; s < 511; s++) {
            float m = mk[s];
            float nd = 0.f, nv = 0.f; int bi = 0;
            if (j < NLB) {
                float e = em[s * NLB + j];
                float mx = -1e30f;
                #pragma unroll
                for (int i = 0; i < NLB; i++) { float v = sd[i] + tc[i]; mx = fmaxf(mx, v); }
                float sum = 0.f;
                #pragma unroll
                for (int i = 0; i < NLB; i++) sum += __expf(sd[i] + tc[i] - mx);
                nd = mx + __logf(sum) + e;
                float bv = -1e30f;
                #pragma unroll
                for (int i = 0; i < NLB; i++) {
                    float v = sv[i] + tc[i];
                    if (v > bv) { bv = v; bi = i; }
                }
                bp[(s - 1) * NLB + j] = (unsigned char)bi;
                nv = bv + e;
            }
            __syncwarp();
            if (j < NLB && m > 0.f) { sd[j] = nd; sv[j] = nv; }
            if (j == 0) {
                int t = tg[s];
                num += m * (tr[prev * NLB + t] + em[s * NLB + t]);
                if (m > 0.f) prev = t;
            }
            __syncwarp();
        }

        if (j == 0) {
            num += endv[prev];
            float mx = -1e30f;
            #pragma unroll
            for (int i = 0; i < NLB; i++) mx = fmaxf(mx, sd[i] + endv[i]);
            float sum = 0.f;
            #pragma unroll
            for (int i = 0; i < NLB; i++) sum += __expf(sd[i] + endv[i] - mx);
            float den = mx + __logf(sum);
            llh[b] = num - den;

            float bv = -1e30f; int last = 0;
            #pragma unroll
            for (int i = 0; i < NLB; i++) {
                float v = sv[i] + endv[i];
                if (v > bv) { bv = v; last = i; }
            }
            float* pd = dout + 1 + (size_t)b * 511;
            pd[510] = (float)last;
            for (int s = 509; s >= 0; s--) {
                last = bp[s * NLB + last];
                pd[s] = (float)last;
            }
        }
    }
}

__global__ void loss_kernel(const float* __restrict__ llh, float* __restrict__ dout)
{
    if (threadIdx.x == 0) {
        float s = 0.f;
        for (int i = 0; i < NB; i++) s += llh[i];
        dout[0] = -s / (float)NB;
    }
}

// ---------------- launcher ----------------
extern "C" void kernel_launch(void* const* d_in, const int* in_sizes, int n_in,
                              void* d_out, int out_size)
{
    (void)in_sizes; (void)n_in; (void)out_size;
    const int*   ids  = (const int*)d_in[0];
    const int*   am   = (const int*)d_in[1];
    const int*   tti  = (const int*)d_in[2];
    const int*   lab  = (const int*)d_in[3];
    const float* we   = (const float*)d_in[4];
    const float* pe   = (const float*)d_in[5];
    const float* te   = (const float*)d_in[6];
    const float* elns = (const float*)d_in[7];
    const float* elnb = (const float*)d_in[8];
    const float* Wqkv = (const float*)d_in[9];
    const float* bqkv = (const float*)d_in[10];
    const float* Wo   = (const float*)d_in[11];
    const float* bo   = (const float*)d_in[12];
    const float* l1s  = (const float*)d_in[13];
    const float* l1b  = (const float*)d_in[14];
    const float* W1   = (const float*)d_in[15];
    const float* b1   = (const float*)d_in[16];
    const float* W2   = (const float*)d_in[17];
    const float* b2   = (const float*)d_in[18];
    const float* l2s  = (const float*)d_in[19];
    const float* l2b  = (const float*)d_in[20];
    const float* Wcls = (const float*)d_in[21];
    const float* bcls = (const float*)d_in[22];
    const float* cst  = (const float*)d_in[23];
    const float* cen  = (const float*)d_in[24];
    const float* ctr  = (const float*)d_in[25];
    float* out = (float*)d_out;

    float *x, *y, *lg, *llh;
    __half *xh, *xl, *qkvh, *qkvl, *ctxh, *ctxl, *ffh, *ffl;
    __half *wqh, *wql, *woh, *wol, *w1h, *w1l, *w2h, *w2l;
    cudaGetSymbolAddress((void**)&x,   g_x);
    cudaGetSymbolAddress((void**)&y,   g_y);
    cudaGetSymbolAddress((void**)&lg,  g_logits);
    cudaGetSymbolAddress((void**)&llh, g_llh);
    cudaGetSymbolAddress((void**)&xh,   g_xh);   cudaGetSymbolAddress((void**)&xl,   g_xl);
    cudaGetSymbolAddress((void**)&qkvh, g_qkvh); cudaGetSymbolAddress((void**)&qkvl, g_qkvl);
    cudaGetSymbolAddress((void**)&ctxh, g_ctxh); cudaGetSymbolAddress((void**)&ctxl, g_ctxl);
    cudaGetSymbolAddress((void**)&ffh,  g_ffh);  cudaGetSymbolAddress((void**)&ffl,  g_ffl);
    cudaGetSymbolAddress((void**)&wqh,  g_wqh);  cudaGetSymbolAddress((void**)&wql,  g_wql);
    cudaGetSymbolAddress((void**)&woh,  g_woh);  cudaGetSymbolAddress((void**)&wol,  g_wol);
    cudaGetSymbolAddress((void**)&w1h,  g_w1h);  cudaGetSymbolAddress((void**)&w1l,  g_w1l);
    cudaGetSymbolAddress((void**)&w2h,  g_w2h);  cudaGetSymbolAddress((void**)&w2l,  g_w2l);

    cudaFuncSetAttribute(attn_fused, cudaFuncAttributeMaxDynamicSharedMemorySize, ATTN_SMEM);
    cudaFuncSetAttribute(gemm_h<0>, cudaFuncAttributeMaxDynamicSharedMemorySize, GEMM_SMEM);
    cudaFuncSetAttribute(gemm_h<1>, cudaFuncAttributeMaxDynamicSharedMemorySize, GEMM_SMEM);
    cudaFuncSetAttribute(gemm_h<2>, cudaFuncAttributeMaxDynamicSharedMemorySize, GEMM_SMEM);

    // weight splits (once per launch)
    {
        int n;
        n = NLAY * HD * T3;  split_kernel<<<(n / 4 + 255) / 256, 256>>>(Wqkv, wqh, wql, n);
        n = NLAY * HD * HD;  split_kernel<<<(n / 4 + 255) / 256, 256>>>(Wo,   woh, wol, n);
        n = NLAY * HD * DFF; split_kernel<<<(n / 4 + 255) / 256, 256>>>(W1,   w1h, w1l, n);
        n = NLAY * DFF * HD; split_kernel<<<(n / 4 + 255) / 256, 256>>>(W2,   w2h, w2l, n);
    }

    embed_ln_kernel<<<TOK, 256>>>(ids, tti, we, pe, te, elns, elnb, x, xh, xl);

    for (int l = 0; l < NLAY; l++) {
        gemm_h<2><<<dim3(T3 / 128, TOK / 128), 256, GEMM_SMEM>>>(
            xh, xl, wqh + (size_t)l * HD * T3, wql + (size_t)l * HD * T3,
            bqkv + (size_t)l * T3, nullptr, qkvh, qkvl, TOK, T3, HD);
        attn_fused<<<dim3(4, NBH), 256, ATTN_SMEM>>>(qkvh, qkvl, am, ctxh, ctxl);
        gemm_h<0><<<dim3(HD / 128, TOK / 128), 256, GEMM_SMEM>>>(
            ctxh, ctxl, woh + (size_t)l * HD * HD, wol + (size_t)l * HD * HD,
            bo + (size_t)l * HD, y, nullptr, nullptr, TOK, HD, HD);
        ln_res_kernel<<<TOK, 256>>>(x, y, l1s + (size_t)l * HD, l1b + (size_t)l * HD, x, xh, xl);
        gemm_h<1><<<dim3(DFF / 128, TOK / 128), 256, GEMM_SMEM>>>(
            xh, xl, w1h + (size_t)l * HD * DFF, w1l + (size_t)l * HD * DFF,
            b1 + (size_t)l * DFF, nullptr, ffh, ffl, TOK, DFF, HD);
        gemm_h<0><<<dim3(HD / 128, TOK / 128), 256, GEMM_SMEM>>>(
            ffh, ffl, w2h + (size_t)l * DFF * HD, w2l + (size_t)l * DFF * HD,
            b2 + (size_t)l * HD, y, nullptr, nullptr, TOK, HD, DFF);
        ln_res_kernel<<<TOK, 256>>>(x, y, l2s + (size_t)l * HD, l2b + (size_t)l * HD, x, xh, xl);
    }

    cls_kernel<<<(TOK * NLB + 255) / 256, 256>>>(x, Wcls, bcls, lg);
    crf_kernel<<<NB, 128>>>(lg, lab, am, cst, cen, ctr, llh, out);
    loss_kernel<<<1, 32>>>(llh, out);
}

// round 13
// speedup vs baseline: 1.1340x; 1.1340x over previous
#include <cuda_runtime.h>
#include <cuda_fp16.h>
#include <math.h>
#include <stdint.h>

// ---------------- problem constants ----------------
#define NB   16
#define NT   512
#define TOK  (NB*NT)        // 8192 tokens
#define HD   768
#define T3   (3*HD)         // 2304
#define DFF  3072
#define NHH  12
#define DH   64
#define NLB  9
#define NBH  (NB*NHH)       // 192
#define NLAY 4

// ---------------- scratch (static device globals; no runtime alloc) ----------------
__device__ float g_x[TOK*HD];
__device__ float g_y[TOK*HD];
__device__ float g_logits[TOK*NLB];
__device__ float g_llh[NB];

__device__ __half g_xh[TOK*HD],   g_xl[TOK*HD];
__device__ __half g_qkvh[TOK*T3], g_qkvl[TOK*T3];
__device__ __half g_ctxh[TOK*HD], g_ctxl[TOK*HD];
__device__ __half g_ffh[TOK*DFF], g_ffl[TOK*DFF];
__device__ __half g_wqh[NLAY*HD*T3],  g_wql[NLAY*HD*T3];
__device__ __half g_woh[NLAY*HD*HD],  g_wol[NLAY*HD*HD];
__device__ __half g_w1h[NLAY*HD*DFF], g_w1l[NLAY*HD*DFF];
__device__ __half g_w2h[NLAY*DFF*HD], g_w2l[NLAY*DFF*HD];

// ---------------- helpers ----------------
__device__ __forceinline__ uint32_t s2u(const void* p) {
    uint32_t a;
    asm("{ .reg .u64 t; cvta.to.shared.u64 t, %1; cvt.u32.u64 %0, t; }" : "=r"(a) : "l"(p));
    return a;
}
__device__ __forceinline__ void splitpack(float a, float b, uint32_t& H, uint32_t& L) {
    __half2 h = __floats2half2_rn(a, b);
    float2 hf = __half22float2(h);
    __half2 l = __floats2half2_rn(a - hf.x, b - hf.y);
    H = *(uint32_t*)&h;
    L = *(uint32_t*)&l;
}
__device__ __forceinline__ void ldmx4(uint32_t* r, uint32_t addr) {
    asm volatile("ldmatrix.sync.aligned.m8n8.x4.shared.b16 {%0,%1,%2,%3}, [%4];"
        : "=r"(r[0]), "=r"(r[1]), "=r"(r[2]), "=r"(r[3]) : "r"(addr));
}
__device__ __forceinline__ void ldmx2(uint32_t* r, uint32_t addr) {
    asm volatile("ldmatrix.sync.aligned.m8n8.x2.shared.b16 {%0,%1}, [%2];"
        : "=r"(r[0]), "=r"(r[1]) : "r"(addr));
}
__device__ __forceinline__ void ldmx2t(uint32_t* r, uint32_t addr) {
    asm volatile("ldmatrix.sync.aligned.m8n8.x2.trans.shared.b16 {%0,%1}, [%2];"
        : "=r"(r[0]), "=r"(r[1]) : "r"(addr));
}
__device__ __forceinline__ void mma16816(float* c, const uint32_t* a, const uint32_t* b) {
    asm volatile(
        "mma.sync.aligned.m16n8k16.row.col.f32.f16.f16.f32 "
        "{%0,%1,%2,%3}, {%4,%5,%6,%7}, {%8,%9}, {%0,%1,%2,%3};"
        : "+f"(c[0]), "+f"(c[1]), "+f"(c[2]), "+f"(c[3])
        : "r"(a[0]), "r"(a[1]), "r"(a[2]), "r"(a[3]), "r"(b[0]), "r"(b[1]));
}
__device__ __forceinline__ float gelu_tanh(float v) {
    float u = 0.7978845608028654f * (v + 0.044715f * v * v * v);
    return 0.5f * v * (1.f + tanhf(u));
}

// ---------------- fp32 -> split half (weights) ----------------
__global__ void __launch_bounds__(256) split_kernel(
    const float* __restrict__ s, __half* __restrict__ h, __half* __restrict__ l, int n)
{
    int i = (blockIdx.x * blockDim.x + threadIdx.x) * 4;
    if (i >= n) return;
    float4 v = *(const float4*)(s + i);
    uint32_t H0, L0, H1, L1;
    splitpack(v.x, v.y, H0, L0);
    splitpack(v.z, v.w, H1, L1);
    *(uint32_t*)(h + i) = H0; *(uint32_t*)(h + i + 2) = H1;
    *(uint32_t*)(l + i) = L0; *(uint32_t*)(l + i + 2) = L1;
}

// ================= 3xFP16 GEMM, double-buffered SMEM pipeline =================
// C = A @ B + bias.  EPI: 0 -> fp32 C; 1 -> half CH/CL + gelu; 2 -> half CH/CL.
// Stage layout (bytes): AH 0 (128x40h), AL 10240, BH 20480 (32x136h), BL 29184. Stage stride 37888.
#define G_STAGE 37888
#define GEMM_SMEM (2*G_STAGE)
template<int EPI>
__global__ void __launch_bounds__(256) gemm_h(
    const __half* __restrict__ AH, const __half* __restrict__ AL,
    const __half* __restrict__ BH, const __half* __restrict__ BL,
    const float* __restrict__ bias,
    float* __restrict__ Cf, __half* __restrict__ CH, __half* __restrict__ CL,
    int M, int N, int K)
{
    extern __shared__ char smem[];
    uint32_t sb = s2u(smem);

    const int tid = threadIdx.x, warp = tid >> 5, lane = tid & 31;
    const int m0 = blockIdx.y * 128, n0 = blockIdx.x * 128;
    const int wm = (warp >> 2) * 64, wn = (warp & 3) * 32;
    const int g = lane >> 2, tg = lane & 3;

    const int am = tid >> 1, ac = (tid & 1) * 16;
    const int bk = tid >> 3, bn = (tid & 7) * 16;
    const __half* AHp = AH + (size_t)(m0 + am) * K + ac;
    const __half* ALp = AL + (size_t)(m0 + am) * K + ac;
    const __half* BHp = BH + n0 + bn;
    const __half* BLp = BL + n0 + bn;

    uint32_t aoff = (uint32_t)((wm + (lane & 15)) * 80 + (lane >> 4) * 16);
    uint32_t boff = (uint32_t)(((lane & 7) + 8 * ((lane >> 3) & 1)) * 272 + wn * 2);
    const uint32_t aW = (uint32_t)(am * 80 + ac * 2);
    const uint32_t bW = (uint32_t)(bk * 272 + bn * 2);

    uint4 rah[2], ral[2], rbh[2], rbl[2];
    rah[0] = *(const uint4*)(AHp);     rah[1] = *(const uint4*)(AHp + 8);
    ral[0] = *(const uint4*)(ALp);     ral[1] = *(const uint4*)(ALp + 8);
    rbh[0] = *(const uint4*)(BHp + (size_t)bk * N);
    rbh[1] = *(const uint4*)(BHp + (size_t)bk * N + 8);
    rbl[0] = *(const uint4*)(BLp + (size_t)bk * N);
    rbl[1] = *(const uint4*)(BLp + (size_t)bk * N + 8);

    float acc[16][4];
    #pragma unroll
    for (int i = 0; i < 16; i++) { acc[i][0] = acc[i][1] = acc[i][2] = acc[i][3] = 0.f; }

    // store stage 0
    {
        char* stp = smem;
        *(uint4*)(stp + aW) = rah[0];          *(uint4*)(stp + aW + 16) = rah[1];
        *(uint4*)(stp + 10240 + aW) = ral[0];  *(uint4*)(stp + 10240 + aW + 16) = ral[1];
        *(uint4*)(stp + 20480 + bW) = rbh[0];  *(uint4*)(stp + 20480 + bW + 16) = rbh[1];
        *(uint4*)(stp + 29184 + bW) = rbl[0];  *(uint4*)(stp + 29184 + bW + 16) = rbl[1];
    }
    __syncthreads();

    const int Tn = K >> 5;
    for (int t = 0; t < Tn; t++) {
        const int st = t & 1;
        if (t + 1 < Tn) {
            int k0 = (t + 1) << 5;
            rah[0] = *(const uint4*)(AHp + k0);     rah[1] = *(const uint4*)(AHp + k0 + 8);
            ral[0] = *(const uint4*)(ALp + k0);     ral[1] = *(const uint4*)(ALp + k0 + 8);
            rbh[0] = *(const uint4*)(BHp + (size_t)(k0 + bk) * N);
            rbh[1] = *(const uint4*)(BHp + (size_t)(k0 + bk) * N + 8);
            rbl[0] = *(const uint4*)(BLp + (size_t)(k0 + bk) * N);
            rbl[1] = *(const uint4*)(BLp + (size_t)(k0 + bk) * N + 8);
        }
        const uint32_t aHb = sb + st * G_STAGE;
        const uint32_t aLb = aHb + 10240;
        const uint32_t bHb = aHb + 20480;
        const uint32_t bLb = aHb + 29184;
        #pragma unroll
        for (int kk = 0; kk < 2; kk++) {
            uint32_t aHf[4][4], aLf[4][4], bHf[4][2], bLf[4][2];
            #pragma unroll
            for (int mf = 0; mf < 4; mf++) {
                ldmx4(aHf[mf], aHb + aoff + mf * 1280 + kk * 32);
                ldmx4(aLf[mf], aLb + aoff + mf * 1280 + kk * 32);
            }
            #pragma unroll
            for (int nf = 0; nf < 4; nf++) {
                ldmx2t(bHf[nf], bHb + boff + nf * 16 + kk * 4352);
                ldmx2t(bLf[nf], bLb + boff + nf * 16 + kk * 4352);
            }
            #pragma unroll
            for (int mf = 0; mf < 4; mf++)
                #pragma unroll
                for (int nf = 0; nf < 4; nf++) {
                    float* c = acc[mf * 4 + nf];
                    mma16816(c, aLf[mf], bHf[nf]);
                    mma16816(c, aHf[mf], bLf[nf]);
                    mma16816(c, aHf[mf], bHf[nf]);
                }
        }
        if (t + 1 < Tn) {
            char* stp = smem + (st ^ 1) * G_STAGE;
            *(uint4*)(stp + aW) = rah[0];          *(uint4*)(stp + aW + 16) = rah[1];
            *(uint4*)(stp + 10240 + aW) = ral[0];  *(uint4*)(stp + 10240 + aW + 16) = ral[1];
            *(uint4*)(stp + 20480 + bW) = rbh[0];  *(uint4*)(stp + 20480 + bW + 16) = rbh[1];
            *(uint4*)(stp + 29184 + bW) = rbl[0];  *(uint4*)(stp + 29184 + bW + 16) = rbl[1];
        }
        __syncthreads();
    }

    #pragma unroll
    for (int mf = 0; mf < 4; mf++)
        #pragma unroll
        for (int nf = 0; nf < 4; nf++) {
            const float* c = acc[mf * 4 + nf];
            int mrow = m0 + wm + mf * 16 + g;
            int ncol = n0 + wn + nf * 8 + tg * 2;
            float b0 = bias[ncol], b1 = bias[ncol + 1];
            float v0 = c[0] + b0, v1 = c[1] + b1, v2 = c[2] + b0, v3 = c[3] + b1;
            if (EPI == 1) { v0 = gelu_tanh(v0); v1 = gelu_tanh(v1); v2 = gelu_tanh(v2); v3 = gelu_tanh(v3); }
            if (EPI == 0) {
                Cf[(size_t)mrow * N + ncol]           = v0;
                Cf[(size_t)mrow * N + ncol + 1]       = v1;
                Cf[(size_t)(mrow + 8) * N + ncol]     = v2;
                Cf[(size_t)(mrow + 8) * N + ncol + 1] = v3;
            } else {
                uint32_t H, L;
                splitpack(v0, v1, H, L);
                *(uint32_t*)&CH[(size_t)mrow * N + ncol] = H;
                *(uint32_t*)&CL[(size_t)mrow * N + ncol] = L;
                splitpack(v2, v3, H, L);
                *(uint32_t*)&CH[(size_t)(mrow + 8) * N + ncol] = H;
                *(uint32_t*)&CL[(size_t)(mrow + 8) * N + ncol] = L;
            }
        }
}

// ================= fused flash attention (3xFP16 mma, online softmax) =================
// grid: (4 m-tiles, NBH). 256 threads, 8 warps x 16 query rows.
// Key tiles of 64, 8 iterations; next K/V tile prefetched into registers during mma.
#define ATTN_SMEM (73984)
__global__ void __launch_bounds__(256, 1) attn_fused(
    const __half* __restrict__ QKVH, const __half* __restrict__ QKVL,
    const int* __restrict__ amask,
    __half* __restrict__ CTXH, __half* __restrict__ CTXL)
{
    extern __shared__ char smraw[];
    __half* QsH = (__half*)smraw;          // [128][72]
    __half* QsL = QsH + 128 * 72;
    __half* KsH = QsL + 128 * 72;          // [64][72]
    __half* KsL = KsH + 64 * 72;
    __half* VsH = KsL + 64 * 72;           // [64][72]
    __half* VsL = VsH + 64 * 72;
    float*  mkf = (float*)(VsL + 64 * 72); // [64]

    const int tid = threadIdx.x, warp = tid >> 5, lane = tid & 31;
    const int bh = blockIdx.y, b = bh / NHH, h = bh % NHH;
    const int m0 = blockIdx.x * 128;
    const int g = lane >> 2, tg = lane & 3;

    // stage Q tile (pre-split halves straight from qkv)
    {
        int am = tid >> 1, ac = (tid & 1) * 32;
        const __half* qh = QKVH + (size_t)(b * NT + m0 + am) * T3 + h * DH + ac;
        const __half* ql = QKVL + (size_t)(b * NT + m0 + am) * T3 + h * DH + ac;
        #pragma unroll
        for (int i = 0; i < 4; i++) {
            *(uint4*)&QsH[am * 72 + ac + i * 8] = *(const uint4*)(qh + i * 8);
            *(uint4*)&QsL[am * 72 + ac + i * 8] = *(const uint4*)(ql + i * 8);
        }
    }
    __syncthreads();

    uint32_t qsHb = s2u(QsH), qsLb = s2u(QsL);
    uint32_t ksHb = s2u(KsH), ksLb = s2u(KsL);
    uint32_t vsHb = s2u(VsH), vsLb = s2u(VsL);
    uint32_t qoff = (uint32_t)((warp * 16 + (lane & 15)) * 144 + (lane >> 4) * 16);
    uint32_t koff = (uint32_t)((lane & 7) * 144 + ((lane >> 3) & 1) * 16);
    uint32_t voff = (uint32_t)(((lane & 7) + 8 * ((lane >> 3) & 1)) * 144);

    uint32_t qH[4][4], qL[4][4];
    #pragma unroll
    for (int kc = 0; kc < 4; kc++) {
        ldmx4(qH[kc], qsHb + qoff + kc * 32);
        ldmx4(qL[kc], qsLb + qoff + kc * 32);
    }

    float o[8][4];
    #pragma unroll
    for (int i = 0; i < 8; i++) { o[i][0] = o[i][1] = o[i][2] = o[i][3] = 0.f; }
    float mA = -1e30f, mB = -1e30f, lA = 0.f, lB = 0.f;

    const int krow = tid >> 2, kseg = (tid & 3) * 16;
    const __half* KHp = QKVH + (size_t)(b * NT + krow) * T3 + HD + h * DH + kseg;
    const __half* KLp = QKVL + (size_t)(b * NT + krow) * T3 + HD + h * DH + kseg;
    const __half* VHp = KHp + HD;
    const __half* VLp = KLp + HD;
    const size_t kstride = (size_t)64 * T3;

    // prefetch tile 0
    uint4 rk[2], rkl[2], rv[2], rvl[2];
    int pmask = 0;
    rk[0]  = *(const uint4*)(KHp);      rk[1]  = *(const uint4*)(KHp + 8);
    rkl[0] = *(const uint4*)(KLp);      rkl[1] = *(const uint4*)(KLp + 8);
    rv[0]  = *(const uint4*)(VHp);      rv[1]  = *(const uint4*)(VHp + 8);
    rvl[0] = *(const uint4*)(VLp);      rvl[1] = *(const uint4*)(VLp + 8);
    if (tid < 64) pmask = amask[b * NT + tid];

    for (int kt = 0; kt < 8; kt++) {
        // store prefetched tile
        *(uint4*)&KsH[krow * 72 + kseg]     = rk[0];
        *(uint4*)&KsH[krow * 72 + kseg + 8] = rk[1];
        *(uint4*)&KsL[krow * 72 + kseg]     = rkl[0];
        *(uint4*)&KsL[krow * 72 + kseg + 8] = rkl[1];
        *(uint4*)&VsH[krow * 72 + kseg]     = rv[0];
        *(uint4*)&VsH[krow * 72 + kseg + 8] = rv[1];
        *(uint4*)&VsL[krow * 72 + kseg]     = rvl[0];
        *(uint4*)&VsL[krow * 72 + kseg + 8] = rvl[1];
        if (tid < 64) mkf[tid] = (1.f - (float)pmask) * -1e9f;
        __syncthreads();

        // prefetch next tile (overlaps with mma below)
        if (kt + 1 < 8) {
            size_t off = (size_t)(kt + 1) * kstride;
            rk[0]  = *(const uint4*)(KHp + off);      rk[1]  = *(const uint4*)(KHp + off + 8);
            rkl[0] = *(const uint4*)(KLp + off);      rkl[1] = *(const uint4*)(KLp + off + 8);
            rv[0]  = *(const uint4*)(VHp + off);      rv[1]  = *(const uint4*)(VHp + off + 8);
            rvl[0] = *(const uint4*)(VLp + off);      rvl[1] = *(const uint4*)(VLp + off + 8);
            if (tid < 64) pmask = amask[b * NT + (kt + 1) * 64 + tid];
        }

        // S = Q @ K^T for this 16x64 warp tile
        float s[8][4];
        #pragma unroll
        for (int i = 0; i < 8; i++) { s[i][0] = s[i][1] = s[i][2] = s[i][3] = 0.f; }
        #pragma unroll
        for (int nf = 0; nf < 8; nf++) {
            #pragma unroll
            for (int kc = 0; kc < 4; kc++) {
                uint32_t bH[2], bL[2];
                ldmx2(bH, ksHb + koff + nf * 1152 + kc * 32);
                ldmx2(bL, ksLb + koff + nf * 1152 + kc * 32);
                mma16816(s[nf], qL[kc], bH);
                mma16816(s[nf], qH[kc], bL);
                mma16816(s[nf], qH[kc], bH);
            }
        }

        // scale + mask, row max
        float rmA = -1e30f, rmB = -1e30f;
        #pragma unroll
        for (int nf = 0; nf < 8; nf++) {
            float d0 = mkf[nf * 8 + tg * 2], d1 = mkf[nf * 8 + tg * 2 + 1];
            s[nf][0] = s[nf][0] * 0.125f + d0;
            s[nf][1] = s[nf][1] * 0.125f + d1;
            s[nf][2] = s[nf][2] * 0.125f + d0;
            s[nf][3] = s[nf][3] * 0.125f + d1;
            rmA = fmaxf(rmA, fmaxf(s[nf][0], s[nf][1]));
            rmB = fmaxf(rmB, fmaxf(s[nf][2], s[nf][3]));
        }
        rmA = fmaxf(rmA, __shfl_xor_sync(0xffffffffu, rmA, 1));
        rmA = fmaxf(rmA, __shfl_xor_sync(0xffffffffu, rmA, 2));
        rmB = fmaxf(rmB, __shfl_xor_sync(0xffffffffu, rmB, 1));
        rmB = fmaxf(rmB, __shfl_xor_sync(0xffffffffu, rmB, 2));

        float nmA = fmaxf(mA, rmA), nmB = fmaxf(mB, rmB);
        float cA = __expf(mA - nmA), cB = __expf(mB - nmB);
        float rsA = 0.f, rsB = 0.f;
        #pragma unroll
        for (int nf = 0; nf < 8; nf++) {
            s[nf][0] = __expf(s[nf][0] - nmA);
            s[nf][1] = __expf(s[nf][1] - nmA);
            s[nf][2] = __expf(s[nf][2] - nmB);
            s[nf][3] = __expf(s[nf][3] - nmB);
            rsA += s[nf][0] + s[nf][1];
            rsB += s[nf][2] + s[nf][3];
        }
        rsA += __shfl_xor_sync(0xffffffffu, rsA, 1);
        rsA += __shfl_xor_sync(0xffffffffu, rsA, 2);
        rsB += __shfl_xor_sync(0xffffffffu, rsB, 1);
        rsB += __shfl_xor_sync(0xffffffffu, rsB, 2);
        lA = lA * cA + rsA;
        lB = lB * cB + rsB;
        mA = nmA; mB = nmB;
        #pragma unroll
        for (int i = 0; i < 8; i++) {
            o[i][0] *= cA; o[i][1] *= cA;
            o[i][2] *= cB; o[i][3] *= cB;
        }

        // O += P @ V   (P from S fragments directly, split hi/lo)
        #pragma unroll
        for (int kc = 0; kc < 4; kc++) {
            uint32_t pH[4], pL[4];
            splitpack(s[2 * kc][0],     s[2 * kc][1],     pH[0], pL[0]);
            splitpack(s[2 * kc][2],     s[2 * kc][3],     pH[1], pL[1]);
            splitpack(s[2 * kc + 1][0], s[2 * kc + 1][1], pH[2], pL[2]);
            splitpack(s[2 * kc + 1][2], s[2 * kc + 1][3], pH[3], pL[3]);
            #pragma unroll
            for (int nf = 0; nf < 8; nf++) {
                uint32_t vH[2], vL[2];
                ldmx2t(vH, vsHb + voff + nf * 16 + kc * 2304);
                ldmx2t(vL, vsLb + voff + nf * 16 + kc * 2304);
                mma16816(o[nf], pL, vH);
                mma16816(o[nf], pH, vL);
                mma16816(o[nf], pH, vH);
            }
        }
        __syncthreads();   // tile fully consumed before next store
    }

    // epilogue: O / l, split to halves
    float iA = 1.f / lA, iB = 1.f / lB;
    int rowA = b * NT + m0 + warp * 16 + g;
    #pragma unroll
    for (int nf = 0; nf < 8; nf++) {
        int ncol = h * DH + nf * 8 + tg * 2;
        uint32_t H, L;
        splitpack(o[nf][0] * iA, o[nf][1] * iA, H, L);
        *(uint32_t*)&CTXH[(size_t)rowA * HD + ncol] = H;
        *(uint32_t*)&CTXL[(size_t)rowA * HD + ncol] = L;
        splitpack(o[nf][2] * iB, o[nf][3] * iB, H, L);
        *(uint32_t*)&CTXH[(size_t)(rowA + 8) * HD + ncol] = H;
        *(uint32_t*)&CTXL[(size_t)(rowA + 8) * HD + ncol] = L;
    }
}

// ---------------- reductions ----------------
__device__ __forceinline__ void reduce2_256(float& a, float& b) {
    __shared__ float sa[8], sb[8];
    #pragma unroll
    for (int o = 16; o; o >>= 1) {
        a += __shfl_xor_sync(0xffffffffu, a, o);
        b += __shfl_xor_sync(0xffffffffu, b, o);
    }
    int w = threadIdx.x >> 5;
    if ((threadIdx.x & 31) == 0) { sa[w] = a; sb[w] = b; }
    __syncthreads();
    a = 0.f; b = 0.f;
    #pragma unroll
    for (int i = 0; i < 8; i++) { a += sa[i]; b += sb[i]; }
}

// ---------------- embedding + LN ----------------
__global__ void __launch_bounds__(256) embed_ln_kernel(
    const int* __restrict__ ids, const int* __restrict__ tt,
    const float* __restrict__ we, const float* __restrict__ pe, const float* __restrict__ te,
    const float* __restrict__ sc, const float* __restrict__ bi,
    float* __restrict__ x, __half* __restrict__ xh, __half* __restrict__ xl)
{
    int tok = blockIdx.x;
    int t   = tok & (NT - 1);
    int tid = threadIdx.x;
    const float* w  = we + (size_t)ids[tok] * HD;
    const float* p  = pe + (size_t)t * HD;
    const float* ty = te + (size_t)tt[tok] * HD;
    float e[3]; float sum = 0.f, sq = 0.f;
    #pragma unroll
    for (int i = 0; i < 3; i++) {
        int c = tid + i * 256;
        float v = w[c] + p[c] + ty[c];
        e[i] = v; sum += v; sq += v * v;
    }
    reduce2_256(sum, sq);
    float mean = sum * (1.f / HD);
    float var  = sq * (1.f / HD) - mean * mean;
    float inv  = rsqrtf(var + 1e-12f);
    #pragma unroll
    for (int i = 0; i < 3; i++) {
        int c = tid + i * 256;
        float v = (e[i] - mean) * inv * sc[c] + bi[c];
        size_t idx = (size_t)tok * HD + c;
        x[idx] = v;
        __half h = __float2half_rn(v);
        xh[idx] = h;
        xl[idx] = __float2half_rn(v - __half2float(h));
    }
}

// ---------------- residual + LN ----------------
__global__ void __launch_bounds__(256) ln_res_kernel(
    const float* __restrict__ xin, const float* __restrict__ y,
    const float* __restrict__ sc, const float* __restrict__ bi,
    float* __restrict__ xout, __half* __restrict__ xh, __half* __restrict__ xl)
{
    int tok = blockIdx.x;
    int tid = threadIdx.x;
    float e[3]; float sum = 0.f, sq = 0.f;
    #pragma unroll
    for (int i = 0; i < 3; i++) {
        int c = tid + i * 256;
        float v = xin[(size_t)tok * HD + c] + y[(size_t)tok * HD + c];
        e[i] = v; sum += v; sq += v * v;
    }
    reduce2_256(sum, sq);
    float mean = sum * (1.f / HD);
    float var  = sq * (1.f / HD) - mean * mean;
    float inv  = rsqrtf(var + 1e-12f);
    #pragma unroll
    for (int i = 0; i < 3; i++) {
        int c = tid + i * 256;
        float v = (e[i] - mean) * inv * sc[c] + bi[c];
        size_t idx = (size_t)tok * HD + c;
        xout[idx] = v;
        __half h = __float2half_rn(v);
        xh[idx] = h;
        xl[idx] = __float2half_rn(v - __half2float(h));
    }
}

// ---------------- classifier ----------------
__global__ void __launch_bounds__(256) cls_kernel(
    const float* __restrict__ x, const float* __restrict__ W,
    const float* __restrict__ bias, float* __restrict__ out)
{
    int idx = blockIdx.x * blockDim.x + threadIdx.x;
    if (idx >= TOK * NLB) return;
    int tok = idx / NLB, n = idx % NLB;
    const float* xr = x + (size_t)tok * HD;
    float s = bias[n];
    #pragma unroll 8
    for (int k = 0; k < HD; k++) s = fmaf(xr[k], W[k * NLB + n], s);
    out[idx] = s;
}

// ---------------- CRF ----------------
__global__ void __launch_bounds__(128) crf_kernel(
    const float* __restrict__ logits, const int* __restrict__ labels,
    const int* __restrict__ amask, const float* __restrict__ startv,
    const float* __restrict__ endv, const float* __restrict__ trans,
    float* __restrict__ llh, float* __restrict__ dout)
{
    __shared__ float em[511 * NLB];
    __shared__ float tr[NLB * NLB];
    __shared__ unsigned char bp[510 * NLB];
    __shared__ float mk[511];
    __shared__ int   tg[511];
    __shared__ float sd[NLB], sv[NLB];

    int b = blockIdx.x, tid = threadIdx.x;
    const float* lp = logits + (size_t)(b * NT + 1) * NLB;
    for (int i = tid; i < 511 * NLB; i += blockDim.x) em[i] = lp[i];
    for (int i = tid; i < NLB * NLB; i += blockDim.x) tr[i] = trans[i];
    for (int i = tid; i < 511; i += blockDim.x) {
        mk[i] = (float)amask[b * NT + 1 + i];
        tg[i] = labels[b * NT + 1 + i];
    }
    __syncthreads();

    if (tid < 32) {
        int j = tid;
        float tc[NLB];
        if (j < NLB) {
            #pragma unroll
            for (int i = 0; i < NLB; i++) tc[i] = tr[i * NLB + j];
            sd[j] = startv[j] + em[j];
            sv[j] = sd[j];
        }
        __syncwarp();
        float num = 0.f; int prev = 0;
        if (j == 0) { prev = tg[0]; num = startv[prev] + em[prev]; }

        for (int s = 1; s < 511; s++) {
            float m = mk[s];
            float nd = 0.f, nv = 0.f; int bi = 0;
            if (j < NLB) {
                float e = em[s * NLB + j];
                float mx = -1e30f;
                #pragma unroll
                for (int i = 0; i < NLB; i++) { float v = sd[i] + tc[i]; mx = fmaxf(mx, v); }
                float sum = 0.f;
                #pragma unroll
                for (int i = 0; i < NLB; i++) sum += __expf(sd[i] + tc[i] - mx);
                nd = mx + __logf(sum) + e;
                float bv = -1e30f;
                #pragma unroll
                for (int i = 0; i < NLB; i++) {
                    float v = sv[i] + tc[i];
                    if (v > bv) { bv = v; bi = i; }
                }
                bp[(s - 1) * NLB + j] = (unsigned char)bi;
                nv = bv + e;
            }
            __syncwarp();
            if (j < NLB && m > 0.f) { sd[j] = nd; sv[j] = nv; }
            if (j == 0) {
                int t = tg[s];
                num += m * (tr[prev * NLB + t] + em[s * NLB + t]);
                if (m > 0.f) prev = t;
            }
            __syncwarp();
        }

        if (j == 0) {
            num += endv[prev];
            float mx = -1e30f;
            #pragma unroll
            for (int i = 0; i < NLB; i++) mx = fmaxf(mx, sd[i] + endv[i]);
            float sum = 0.f;
            #pragma unroll
            for (int i = 0; i < NLB; i++) sum += __expf(sd[i] + endv[i] - mx);
            float den = mx + __logf(sum);
            llh[b] = num - den;

            float bv = -1e30f; int last = 0;
            #pragma unroll
            for (int i = 0; i < NLB; i++) {
                float v = sv[i] + endv[i];
                if (v > bv) { bv = v; last = i; }
            }
            float* pd = dout + 1 + (size_t)b * 511;
            pd[510] = (float)last;
            for (int s = 509; s >= 0; s--) {
                last = bp[s * NLB + last];
                pd[s] = (float)last;
            }
        }
    }
}

__global__ void loss_kernel(const float* __restrict__ llh, float* __restrict__ dout)
{
    if (threadIdx.x == 0) {
        float s = 0.f;
        for (int i = 0; i < NB; i++) s += llh[i];
        dout[0] = -s / (float)NB;
    }
}

// ---------------- launcher ----------------
extern "C" void kernel_launch(void* const* d_in, const int* in_sizes, int n_in,
                              void* d_out, int out_size)
{
    (void)in_sizes; (void)n_in; (void)out_size;
    const int*   ids  = (const int*)d_in[0];
    const int*   am   = (const int*)d_in[1];
    const int*   tti  = (const int*)d_in[2];
    const int*   lab  = (const int*)d_in[3];
    const float* we   = (const float*)d_in[4];
    const float* pe   = (const float*)d_in[5];
    const float* te   = (const float*)d_in[6];
    const float* elns = (const float*)d_in[7];
    const float* elnb = (const float*)d_in[8];
    const float* Wqkv = (const float*)d_in[9];
    const float* bqkv = (const float*)d_in[10];
    const float* Wo   = (const float*)d_in[11];
    const float* bo   = (const float*)d_in[12];
    const float* l1s  = (const float*)d_in[13];
    const float* l1b  = (const float*)d_in[14];
    const float* W1   = (const float*)d_in[15];
    const float* b1   = (const float*)d_in[16];
    const float* W2   = (const float*)d_in[17];
    const float* b2   = (const float*)d_in[18];
    const float* l2s  = (const float*)d_in[19];
    const float* l2b  = (const float*)d_in[20];
    const float* Wcls = (const float*)d_in[21];
    const float* bcls = (const float*)d_in[22];
    const float* cst  = (const float*)d_in[23];
    const float* cen  = (const float*)d_in[24];
    const float* ctr  = (const float*)d_in[25];
    float* out = (float*)d_out;

    float *x, *y, *lg, *llh;
    __half *xh, *xl, *qkvh, *qkvl, *ctxh, *ctxl, *ffh, *ffl;
    __half *wqh, *wql, *woh, *wol, *w1h, *w1l, *w2h, *w2l;
    cudaGetSymbolAddress((void**)&x,   g_x);
    cudaGetSymbolAddress((void**)&y,   g_y);
    cudaGetSymbolAddress((void**)&lg,  g_logits);
    cudaGetSymbolAddress((void**)&llh, g_llh);
    cudaGetSymbolAddress((void**)&xh,   g_xh);   cudaGetSymbolAddress((void**)&xl,   g_xl);
    cudaGetSymbolAddress((void**)&qkvh, g_qkvh); cudaGetSymbolAddress((void**)&qkvl, g_qkvl);
    cudaGetSymbolAddress((void**)&ctxh, g_ctxh); cudaGetSymbolAddress((void**)&ctxl, g_ctxl);
    cudaGetSymbolAddress((void**)&ffh,  g_ffh);  cudaGetSymbolAddress((void**)&ffl,  g_ffl);
    cudaGetSymbolAddress((void**)&wqh,  g_wqh);  cudaGetSymbolAddress((void**)&wql,  g_wql);
    cudaGetSymbolAddress((void**)&woh,  g_woh);  cudaGetSymbolAddress((void**)&wol,  g_wol);
    cudaGetSymbolAddress((void**)&w1h,  g_w1h);  cudaGetSymbolAddress((void**)&w1l,  g_w1l);
    cudaGetSymbolAddress((void**)&w2h,  g_w2h);  cudaGetSymbolAddress((void**)&w2l,  g_w2l);

    cudaFuncSetAttribute(attn_fused, cudaFuncAttributeMaxDynamicSharedMemorySize, ATTN_SMEM);
    cudaFuncSetAttribute(gemm_h<0>, cudaFuncAttributeMaxDynamicSharedMemorySize, GEMM_SMEM);
    cudaFuncSetAttribute(gemm_h<1>, cudaFuncAttributeMaxDynamicSharedMemorySize, GEMM_SMEM);
    cudaFuncSetAttribute(gemm_h<2>, cudaFuncAttributeMaxDynamicSharedMemorySize, GEMM_SMEM);

    // weight splits (once per launch)
    {
        int n;
        n = NLAY * HD * T3;  split_kernel<<<(n / 4 + 255) / 256, 256>>>(Wqkv, wqh, wql, n);
        n = NLAY * HD * HD;  split_kernel<<<(n / 4 + 255) / 256, 256>>>(Wo,   woh, wol, n);
        n = NLAY * HD * DFF; split_kernel<<<(n / 4 + 255) / 256, 256>>>(W1,   w1h, w1l, n);
        n = NLAY * DFF * HD; split_kernel<<<(n / 4 + 255) / 256, 256>>>(W2,   w2h, w2l, n);
    }

    embed_ln_kernel<<<TOK, 256>>>(ids, tti, we, pe, te, elns, elnb, x, xh, xl);

    for (int l = 0; l < NLAY; l++) {
        gemm_h<2><<<dim3(T3 / 128, TOK / 128), 256, GEMM_SMEM>>>(
            xh, xl, wqh + (size_t)l * HD * T3, wql + (size_t)l * HD * T3,
            bqkv + (size_t)l * T3, nullptr, qkvh, qkvl, TOK, T3, HD);
        attn_fused<<<dim3(4, NBH), 256, ATTN_SMEM>>>(qkvh, qkvl, am, ctxh, ctxl);
        gemm_h<0><<<dim3(HD / 128, TOK / 128), 256, GEMM_SMEM>>>(
            ctxh, ctxl, woh + (size_t)l * HD * HD, wol + (size_t)l * HD * HD,
            bo + (size_t)l * HD, y, nullptr, nullptr, TOK, HD, HD);
        ln_res_kernel<<<TOK, 256>>>(x, y, l1s + (size_t)l * HD, l1b + (size_t)l * HD, x, xh, xl);
        gemm_h<1><<<dim3(DFF / 128, TOK / 128), 256, GEMM_SMEM>>>(
            xh, xl, w1h + (size_t)l * HD * DFF, w1l + (size_t)l * HD * DFF,
            b1 + (size_t)l * DFF, nullptr, ffh, ffl, TOK, DFF, HD);
        gemm_h<0><<<dim3(HD / 128, TOK / 128), 256, GEMM_SMEM>>>(
            ffh, ffl, w2h + (size_t)l * DFF * HD, w2l + (size_t)l * DFF * HD,
            b2 + (size_t)l * HD, y, nullptr, nullptr, TOK, HD, DFF);
        ln_res_kernel<<<TOK, 256>>>(x, y, l2s + (size_t)l * HD, l2b + (size_t)l * HD, x, xh, xl);
    }

    cls_kernel<<<(TOK * NLB + 255) / 256, 256>>>(x, Wcls, bcls, lg);
    crf_kernel<<<NB, 128>>>(lg, lab, am, cst, cen, ctr, llh, out);
    loss_kernel<<<1, 32>>>(llh, out);
}

// round 14
// speedup vs baseline: 1.2122x; 1.0690x over previous
#include <cuda_runtime.h>
#include <cuda_fp16.h>
#include <math.h>
#include <stdint.h>

// ---------------- problem constants ----------------
#define NB   16
#define NT   512
#define TOK  (NB*NT)        // 8192 tokens
#define HD   768
#define T3   (3*HD)         // 2304
#define DFF  3072
#define NHH  12
#define DH   64
#define NLB  9
#define NBH  (NB*NHH)       // 192
#define NLAY 4

// ---------------- scratch (static device globals; no runtime alloc) ----------------
__device__ float g_x[TOK*HD];
__device__ float g_y[TOK*HD];
__device__ float g_logits[TOK*NLB];
__device__ float g_llh[NB];

__device__ __half g_xh[TOK*HD],   g_xl[TOK*HD];
__device__ __half g_qkvh[TOK*T3], g_qkvl[TOK*T3];
__device__ __half g_ctxh[TOK*HD], g_ctxl[TOK*HD];
__device__ __half g_ffh[TOK*DFF], g_ffl[TOK*DFF];
__device__ __half g_wqh[NLAY*HD*T3],  g_wql[NLAY*HD*T3];
__device__ __half g_woh[NLAY*HD*HD],  g_wol[NLAY*HD*HD];
__device__ __half g_w1h[NLAY*HD*DFF], g_w1l[NLAY*HD*DFF];
__device__ __half g_w2h[NLAY*DFF*HD], g_w2l[NLAY*DFF*HD];

// ---------------- helpers ----------------
__device__ __forceinline__ uint32_t s2u(const void* p) {
    uint32_t a;
    asm("{ .reg .u64 t; cvta.to.shared.u64 t, %1; cvt.u32.u64 %0, t; }" : "=r"(a) : "l"(p));
    return a;
}
__device__ __forceinline__ void splitpack(float a, float b, uint32_t& H, uint32_t& L) {
    __half2 h = __floats2half2_rn(a, b);
    float2 hf = __half22float2(h);
    __half2 l = __floats2half2_rn(a - hf.x, b - hf.y);
    H = *(uint32_t*)&h;
    L = *(uint32_t*)&l;
}
__device__ __forceinline__ void ldmx4(uint32_t* r, uint32_t addr) {
    asm volatile("ldmatrix.sync.aligned.m8n8.x4.shared.b16 {%0,%1,%2,%3}, [%4];"
        : "=r"(r[0]), "=r"(r[1]), "=r"(r[2]), "=r"(r[3]) : "r"(addr));
}
__device__ __forceinline__ void ldmx2(uint32_t* r, uint32_t addr) {
    asm volatile("ldmatrix.sync.aligned.m8n8.x2.shared.b16 {%0,%1}, [%2];"
        : "=r"(r[0]), "=r"(r[1]) : "r"(addr));
}
__device__ __forceinline__ void ldmx2t(uint32_t* r, uint32_t addr) {
    asm volatile("ldmatrix.sync.aligned.m8n8.x2.trans.shared.b16 {%0,%1}, [%2];"
        : "=r"(r[0]), "=r"(r[1]) : "r"(addr));
}
__device__ __forceinline__ void mma16816(float* c, const uint32_t* a, const uint32_t* b) {
    asm volatile(
        "mma.sync.aligned.m16n8k16.row.col.f32.f16.f16.f32 "
        "{%0,%1,%2,%3}, {%4,%5,%6,%7}, {%8,%9}, {%0,%1,%2,%3};"
        : "+f"(c[0]), "+f"(c[1]), "+f"(c[2]), "+f"(c[3])
        : "r"(a[0]), "r"(a[1]), "r"(a[2]), "r"(a[3]), "r"(b[0]), "r"(b[1]));
}
__device__ __forceinline__ float gelu_tanh(float v) {
    float u = 0.7978845608028654f * (v + 0.044715f * v * v * v);
    return 0.5f * v * (1.f + tanhf(u));
}

// ---------------- fp32 -> split half (weights) ----------------
__global__ void __launch_bounds__(256) split_kernel(
    const float* __restrict__ s, __half* __restrict__ h, __half* __restrict__ l, int n)
{
    int i = (blockIdx.x * blockDim.x + threadIdx.x) * 4;
    if (i >= n) return;
    float4 v = *(const float4*)(s + i);
    uint32_t H0, L0, H1, L1;
    splitpack(v.x, v.y, H0, L0);
    splitpack(v.z, v.w, H1, L1);
    *(uint32_t*)(h + i) = H0; *(uint32_t*)(h + i + 2) = H1;
    *(uint32_t*)(l + i) = L0; *(uint32_t*)(l + i + 2) = L1;
}

// ================= 3xFP16 GEMM on pre-split halves (R10 single-buffer winner) =================
// C = A @ B + bias.  EPI: 0 -> fp32 C; 1 -> half CH/CL + gelu; 2 -> half CH/CL.
template<int EPI>
__global__ void __launch_bounds__(256) gemm_h(
    const __half* __restrict__ AH, const __half* __restrict__ AL,
    const __half* __restrict__ BH, const __half* __restrict__ BL,
    const float* __restrict__ bias,
    float* __restrict__ Cf, __half* __restrict__ CH, __half* __restrict__ CL,
    int M, int N, int K)
{
    __shared__ __half AsH[128][40], AsL[128][40];
    __shared__ __half BsH[32][136], BsL[32][136];

    const int tid = threadIdx.x, warp = tid >> 5, lane = tid & 31;
    const int m0 = blockIdx.y * 128, n0 = blockIdx.x * 128;
    const int wm = (warp >> 2) * 64, wn = (warp & 3) * 32;
    const int g = lane >> 2, tg = lane & 3;

    const int am = tid >> 1, ac = (tid & 1) * 16;
    const int bk = tid >> 3, bn = (tid & 7) * 16;
    const __half* AHp = AH + (size_t)(m0 + am) * K + ac;
    const __half* ALp = AL + (size_t)(m0 + am) * K + ac;
    const __half* BHp = BH + n0 + bn;
    const __half* BLp = BL + n0 + bn;

    uint32_t asHb = s2u(&AsH[0][0]), asLb = s2u(&AsL[0][0]);
    uint32_t bsHb = s2u(&BsH[0][0]), bsLb = s2u(&BsL[0][0]);
    uint32_t aoff = (uint32_t)((wm + (lane & 15)) * 80 + (lane >> 4) * 16);
    uint32_t boff = (uint32_t)(((lane & 7) + 8 * ((lane >> 3) & 1)) * 272 + wn * 2);

    uint4 rah[2], ral[2], rbh[2], rbl[2];
    rah[0] = *(const uint4*)(AHp);     rah[1] = *(const uint4*)(AHp + 8);
    ral[0] = *(const uint4*)(ALp);     ral[1] = *(const uint4*)(ALp + 8);
    rbh[0] = *(const uint4*)(BHp + (size_t)bk * N);
    rbh[1] = *(const uint4*)(BHp + (size_t)bk * N + 8);
    rbl[0] = *(const uint4*)(BLp + (size_t)bk * N);
    rbl[1] = *(const uint4*)(BLp + (size_t)bk * N + 8);

    float acc[16][4];
    #pragma unroll
    for (int i = 0; i < 16; i++) { acc[i][0] = acc[i][1] = acc[i][2] = acc[i][3] = 0.f; }

    const int Tn = K >> 5;
    for (int t = 0; t < Tn; t++) {
        *(uint4*)&AsH[am][ac] = rah[0]; *(uint4*)&AsH[am][ac + 8] = rah[1];
        *(uint4*)&AsL[am][ac] = ral[0]; *(uint4*)&AsL[am][ac + 8] = ral[1];
        *(uint4*)&BsH[bk][bn] = rbh[0]; *(uint4*)&BsH[bk][bn + 8] = rbh[1];
        *(uint4*)&BsL[bk][bn] = rbl[0]; *(uint4*)&BsL[bk][bn + 8] = rbl[1];
        __syncthreads();
        if (t + 1 < Tn) {
            int k0 = (t + 1) << 5;
            rah[0] = *(const uint4*)(AHp + k0);     rah[1] = *(const uint4*)(AHp + k0 + 8);
            ral[0] = *(const uint4*)(ALp + k0);     ral[1] = *(const uint4*)(ALp + k0 + 8);
            rbh[0] = *(const uint4*)(BHp + (size_t)(k0 + bk) * N);
            rbh[1] = *(const uint4*)(BHp + (size_t)(k0 + bk) * N + 8);
            rbl[0] = *(const uint4*)(BLp + (size_t)(k0 + bk) * N);
            rbl[1] = *(const uint4*)(BLp + (size_t)(k0 + bk) * N + 8);
        }
        #pragma unroll
        for (int kk = 0; kk < 2; kk++) {
            uint32_t aH[4][4], aL[4][4], bH[4][2], bL[4][2];
            #pragma unroll
            for (int mf = 0; mf < 4; mf++) {
                ldmx4(aH[mf], asHb + aoff + mf * 1280 + kk * 32);
                ldmx4(aL[mf], asLb + aoff + mf * 1280 + kk * 32);
            }
            #pragma unroll
            for (int nf = 0; nf < 4; nf++) {
                ldmx2t(bH[nf], bsHb + boff + nf * 16 + kk * 4352);
                ldmx2t(bL[nf], bsLb + boff + nf * 16 + kk * 4352);
            }
            #pragma unroll
            for (int mf = 0; mf < 4; mf++)
                #pragma unroll
                for (int nf = 0; nf < 4; nf++) {
                    float* c = acc[mf * 4 + nf];
                    mma16816(c, aL[mf], bH[nf]);
                    mma16816(c, aH[mf], bL[nf]);
                    mma16816(c, aH[mf], bH[nf]);
                }
        }
        __syncthreads();
    }

    #pragma unroll
    for (int mf = 0; mf < 4; mf++)
        #pragma unroll
        for (int nf = 0; nf < 4; nf++) {
            const float* c = acc[mf * 4 + nf];
            int mrow = m0 + wm + mf * 16 + g;
            int ncol = n0 + wn + nf * 8 + tg * 2;
            float b0 = bias[ncol], b1 = bias[ncol + 1];
            float v0 = c[0] + b0, v1 = c[1] + b1, v2 = c[2] + b0, v3 = c[3] + b1;
            if (EPI == 1) { v0 = gelu_tanh(v0); v1 = gelu_tanh(v1); v2 = gelu_tanh(v2); v3 = gelu_tanh(v3); }
            if (EPI == 0) {
                Cf[(size_t)mrow * N + ncol]           = v0;
                Cf[(size_t)mrow * N + ncol + 1]       = v1;
                Cf[(size_t)(mrow + 8) * N + ncol]     = v2;
                Cf[(size_t)(mrow + 8) * N + ncol + 1] = v3;
            } else {
                uint32_t H, L;
                splitpack(v0, v1, H, L);
                *(uint32_t*)&CH[(size_t)mrow * N + ncol] = H;
                *(uint32_t*)&CL[(size_t)mrow * N + ncol] = L;
                splitpack(v2, v3, H, L);
                *(uint32_t*)&CH[(size_t)(mrow + 8) * N + ncol] = H;
                *(uint32_t*)&CL[(size_t)(mrow + 8) * N + ncol] = L;
            }
        }
}

// ================= fused flash attention (3xFP16 mma, online softmax, reg prefetch) =================
// grid: (4 m-tiles, NBH). 256 threads, 8 warps x 16 query rows.
#define ATTN_SMEM (73984)
__global__ void __launch_bounds__(256, 1) attn_fused(
    const __half* __restrict__ QKVH, const __half* __restrict__ QKVL,
    const int* __restrict__ amask,
    __half* __restrict__ CTXH, __half* __restrict__ CTXL)
{
    extern __shared__ char smraw[];
    __half* QsH = (__half*)smraw;          // [128][72]
    __half* QsL = QsH + 128 * 72;
    __half* KsH = QsL + 128 * 72;          // [64][72]
    __half* KsL = KsH + 64 * 72;
    __half* VsH = KsL + 64 * 72;           // [64][72]
    __half* VsL = VsH + 64 * 72;
    float*  mkf = (float*)(VsL + 64 * 72); // [64]

    const int tid = threadIdx.x, warp = tid >> 5, lane = tid & 31;
    const int bh = blockIdx.y, b = bh / NHH, h = bh % NHH;
    const int m0 = blockIdx.x * 128;
    const int g = lane >> 2, tg = lane & 3;

    // stage Q tile (pre-split halves straight from qkv)
    {
        int am = tid >> 1, ac = (tid & 1) * 32;
        const __half* qh = QKVH + (size_t)(b * NT + m0 + am) * T3 + h * DH + ac;
        const __half* ql = QKVL + (size_t)(b * NT + m0 + am) * T3 + h * DH + ac;
        #pragma unroll
        for (int i = 0; i < 4; i++) {
            *(uint4*)&QsH[am * 72 + ac + i * 8] = *(const uint4*)(qh + i * 8);
            *(uint4*)&QsL[am * 72 + ac + i * 8] = *(const uint4*)(ql + i * 8);
        }
    }
    __syncthreads();

    uint32_t qsHb = s2u(QsH), qsLb = s2u(QsL);
    uint32_t ksHb = s2u(KsH), ksLb = s2u(KsL);
    uint32_t vsHb = s2u(VsH), vsLb = s2u(VsL);
    uint32_t qoff = (uint32_t)((warp * 16 + (lane & 15)) * 144 + (lane >> 4) * 16);
    uint32_t koff = (uint32_t)((lane & 7) * 144 + ((lane >> 3) & 1) * 16);
    uint32_t voff = (uint32_t)(((lane & 7) + 8 * ((lane >> 3) & 1)) * 144);

    uint32_t qH[4][4], qL[4][4];
    #pragma unroll
    for (int kc = 0; kc < 4; kc++) {
        ldmx4(qH[kc], qsHb + qoff + kc * 32);
        ldmx4(qL[kc], qsLb + qoff + kc * 32);
    }

    float o[8][4];
    #pragma unroll
    for (int i = 0; i < 8; i++) { o[i][0] = o[i][1] = o[i][2] = o[i][3] = 0.f; }
    float mA = -1e30f, mB = -1e30f, lA = 0.f, lB = 0.f;

    const int krow = tid >> 2, kseg = (tid & 3) * 16;
    const __half* KHp = QKVH + (size_t)(b * NT + krow) * T3 + HD + h * DH + kseg;
    const __half* KLp = QKVL + (size_t)(b * NT + krow) * T3 + HD + h * DH + kseg;
    const __half* VHp = KHp + HD;
    const __half* VLp = KLp + HD;
    const size_t kstride = (size_t)64 * T3;

    // prefetch tile 0
    uint4 rk[2], rkl[2], rv[2], rvl[2];
    int pmask = 0;
    rk[0]  = *(const uint4*)(KHp);      rk[1]  = *(const uint4*)(KHp + 8);
    rkl[0] = *(const uint4*)(KLp);      rkl[1] = *(const uint4*)(KLp + 8);
    rv[0]  = *(const uint4*)(VHp);      rv[1]  = *(const uint4*)(VHp + 8);
    rvl[0] = *(const uint4*)(VLp);      rvl[1] = *(const uint4*)(VLp + 8);
    if (tid < 64) pmask = amask[b * NT + tid];

    for (int kt = 0; kt < 8; kt++) {
        // store prefetched tile
        *(uint4*)&KsH[krow * 72 + kseg]     = rk[0];
        *(uint4*)&KsH[krow * 72 + kseg + 8] = rk[1];
        *(uint4*)&KsL[krow * 72 + kseg]     = rkl[0];
        *(uint4*)&KsL[krow * 72 + kseg + 8] = rkl[1];
        *(uint4*)&VsH[krow * 72 + kseg]     = rv[0];
        *(uint4*)&VsH[krow * 72 + kseg + 8] = rv[1];
        *(uint4*)&VsL[krow * 72 + kseg]     = rvl[0];
        *(uint4*)&VsL[krow * 72 + kseg + 8] = rvl[1];
        if (tid < 64) mkf[tid] = (1.f - (float)pmask) * -1e9f;
        __syncthreads();

        // prefetch next tile (overlaps with mma below)
        if (kt + 1 < 8) {
            size_t off = (size_t)(kt + 1) * kstride;
            rk[0]  = *(const uint4*)(KHp + off);      rk[1]  = *(const uint4*)(KHp + off + 8);
            rkl[0] = *(const uint4*)(KLp + off);      rkl[1] = *(const uint4*)(KLp + off + 8);
            rv[0]  = *(const uint4*)(VHp + off);      rv[1]  = *(const uint4*)(VHp + off + 8);
            rvl[0] = *(const uint4*)(VLp + off);      rvl[1] = *(const uint4*)(VLp + off + 8);
            if (tid < 64) pmask = amask[b * NT + (kt + 1) * 64 + tid];
        }

        // S = Q @ K^T for this 16x64 warp tile
        float s[8][4];
        #pragma unroll
        for (int i = 0; i < 8; i++) { s[i][0] = s[i][1] = s[i][2] = s[i][3] = 0.f; }
        #pragma unroll
        for (int nf = 0; nf < 8; nf++) {
            #pragma unroll
            for (int kc = 0; kc < 4; kc++) {
                uint32_t bH[2], bL[2];
                ldmx2(bH, ksHb + koff + nf * 1152 + kc * 32);
                ldmx2(bL, ksLb + koff + nf * 1152 + kc * 32);
                mma16816(s[nf], qL[kc], bH);
                mma16816(s[nf], qH[kc], bL);
                mma16816(s[nf], qH[kc], bH);
            }
        }

        // scale + mask, row max
        float rmA = -1e30f, rmB = -1e30f;
        #pragma unroll
        for (int nf = 0; nf < 8; nf++) {
            float d0 = mkf[nf * 8 + tg * 2], d1 = mkf[nf * 8 + tg * 2 + 1];
            s[nf][0] = s[nf][0] * 0.125f + d0;
            s[nf][1] = s[nf][1] * 0.125f + d1;
            s[nf][2] = s[nf][2] * 0.125f + d0;
            s[nf][3] = s[nf][3] * 0.125f + d1;
            rmA = fmaxf(rmA, fmaxf(s[nf][0], s[nf][1]));
            rmB = fmaxf(rmB, fmaxf(s[nf][2], s[nf][3]));
        }
        rmA = fmaxf(rmA, __shfl_xor_sync(0xffffffffu, rmA, 1));
        rmA = fmaxf(rmA, __shfl_xor_sync(0xffffffffu, rmA, 2));
        rmB = fmaxf(rmB, __shfl_xor_sync(0xffffffffu, rmB, 1));
        rmB = fmaxf(rmB, __shfl_xor_sync(0xffffffffu, rmB, 2));

        float nmA = fmaxf(mA, rmA), nmB = fmaxf(mB, rmB);
        float cA = __expf(mA - nmA), cB = __expf(mB - nmB);
        float rsA = 0.f, rsB = 0.f;
        #pragma unroll
        for (int nf = 0; nf < 8; nf++) {
            s[nf][0] = __expf(s[nf][0] - nmA);
            s[nf][1] = __expf(s[nf][1] - nmA);
            s[nf][2] = __expf(s[nf][2] - nmB);
            s[nf][3] = __expf(s[nf][3] - nmB);
            rsA += s[nf][0] + s[nf][1];
            rsB += s[nf][2] + s[nf][3];
        }
        rsA += __shfl_xor_sync(0xffffffffu, rsA, 1);
        rsA += __shfl_xor_sync(0xffffffffu, rsA, 2);
        rsB += __shfl_xor_sync(0xffffffffu, rsB, 1);
        rsB += __shfl_xor_sync(0xffffffffu, rsB, 2);
        lA = lA * cA + rsA;
        lB = lB * cB + rsB;
        mA = nmA; mB = nmB;
        #pragma unroll
        for (int i = 0; i < 8; i++) {
            o[i][0] *= cA; o[i][1] *= cA;
            o[i][2] *= cB; o[i][3] *= cB;
        }

        // O += P @ V   (P from S fragments directly, split hi/lo)
        #pragma unroll
        for (int kc = 0; kc < 4; kc++) {
            uint32_t pH[4], pL[4];
            splitpack(s[2 * kc][0],     s[2 * kc][1],     pH[0], pL[0]);
            splitpack(s[2 * kc][2],     s[2 * kc][3],     pH[1], pL[1]);
            splitpack(s[2 * kc + 1][0], s[2 * kc + 1][1], pH[2], pL[2]);
            splitpack(s[2 * kc + 1][2], s[2 * kc + 1][3], pH[3], pL[3]);
            #pragma unroll
            for (int nf = 0; nf < 8; nf++) {
                uint32_t vH[2], vL[2];
                ldmx2t(vH, vsHb + voff + nf * 16 + kc * 2304);
                ldmx2t(vL, vsLb + voff + nf * 16 + kc * 2304);
                mma16816(o[nf], pL, vH);
                mma16816(o[nf], pH, vL);
                mma16816(o[nf], pH, vH);
            }
        }
        __syncthreads();   // tile fully consumed before next store
    }

    // epilogue: O / l, split to halves
    float iA = 1.f / lA, iB = 1.f / lB;
    int rowA = b * NT + m0 + warp * 16 + g;
    #pragma unroll
    for (int nf = 0; nf < 8; nf++) {
        int ncol = h * DH + nf * 8 + tg * 2;
        uint32_t H, L;
        splitpack(o[nf][0] * iA, o[nf][1] * iA, H, L);
        *(uint32_t*)&CTXH[(size_t)rowA * HD + ncol] = H;
        *(uint32_t*)&CTXL[(size_t)rowA * HD + ncol] = L;
        splitpack(o[nf][2] * iB, o[nf][3] * iB, H, L);
        *(uint32_t*)&CTXH[(size_t)(rowA + 8) * HD + ncol] = H;
        *(uint32_t*)&CTXL[(size_t)(rowA + 8) * HD + ncol] = L;
    }
}

// ---------------- reductions ----------------
__device__ __forceinline__ void reduce2_256(float& a, float& b) {
    __shared__ float sa[8], sb[8];
    #pragma unroll
    for (int o = 16; o; o >>= 1) {
        a += __shfl_xor_sync(0xffffffffu, a, o);
        b += __shfl_xor_sync(0xffffffffu, b, o);
    }
    int w = threadIdx.x >> 5;
    if ((threadIdx.x & 31) == 0) { sa[w] = a; sb[w] = b; }
    __syncthreads();
    a = 0.f; b = 0.f;
    #pragma unroll
    for (int i = 0; i < 8; i++) { a += sa[i]; b += sb[i]; }
}

// ---------------- embedding + LN ----------------
__global__ void __launch_bounds__(256) embed_ln_kernel(
    const int* __restrict__ ids, const int* __restrict__ tt,
    const float* __restrict__ we, const float* __restrict__ pe, const float* __restrict__ te,
    const float* __restrict__ sc, const float* __restrict__ bi,
    float* __restrict__ x, __half* __restrict__ xh, __half* __restrict__ xl)
{
    int tok = blockIdx.x;
    int t   = tok & (NT - 1);
    int tid = threadIdx.x;
    const float* w  = we + (size_t)ids[tok] * HD;
    const float* p  = pe + (size_t)t * HD;
    const float* ty = te + (size_t)tt[tok] * HD;
    float e[3]; float sum = 0.f, sq = 0.f;
    #pragma unroll
    for (int i = 0; i < 3; i++) {
        int c = tid + i * 256;
        float v = w[c] + p[c] + ty[c];
        e[i] = v; sum += v; sq += v * v;
    }
    reduce2_256(sum, sq);
    float mean = sum * (1.f / HD);
    float var  = sq * (1.f / HD) - mean * mean;
    float inv  = rsqrtf(var + 1e-12f);
    #pragma unroll
    for (int i = 0; i < 3; i++) {
        int c = tid + i * 256;
        float v = (e[i] - mean) * inv * sc[c] + bi[c];
        size_t idx = (size_t)tok * HD + c;
        x[idx] = v;
        __half h = __float2half_rn(v);
        xh[idx] = h;
        xl[idx] = __float2half_rn(v - __half2float(h));
    }
}

// ---------------- residual + LN ----------------
__global__ void __launch_bounds__(256) ln_res_kernel(
    const float* __restrict__ xin, const float* __restrict__ y,
    const float* __restrict__ sc, const float* __restrict__ bi,
    float* __restrict__ xout, __half* __restrict__ xh, __half* __restrict__ xl)
{
    int tok = blockIdx.x;
    int tid = threadIdx.x;
    float e[3]; float sum = 0.f, sq = 0.f;
    #pragma unroll
    for (int i = 0; i < 3; i++) {
        int c = tid + i * 256;
        float v = xin[(size_t)tok * HD + c] + y[(size_t)tok * HD + c];
        e[i] = v; sum += v; sq += v * v;
    }
    reduce2_256(sum, sq);
    float mean = sum * (1.f / HD);
    float var  = sq * (1.f / HD) - mean * mean;
    float inv  = rsqrtf(var + 1e-12f);
    #pragma unroll
    for (int i = 0; i < 3; i++) {
        int c = tid + i * 256;
        float v = (e[i] - mean) * inv * sc[c] + bi[c];
        size_t idx = (size_t)tok * HD + c;
        xout[idx] = v;
        __half h = __float2half_rn(v);
        xh[idx] = h;
        xl[idx] = __float2half_rn(v - __half2float(h));
    }
}

// ---------------- classifier ----------------
__global__ void __launch_bounds__(256) cls_kernel(
    const float* __restrict__ x, const float* __restrict__ W,
    const float* __restrict__ bias, float* __restrict__ out)
{
    int idx = blockIdx.x * blockDim.x + threadIdx.x;
    if (idx >= TOK * NLB) return;
    int tok = idx / NLB, n = idx % NLB;
    const float* xr = x + (size_t)tok * HD;
    float s = bias[n];
    #pragma unroll 8
    for (int k = 0; k < HD; k++) s = fmaf(xr[k], W[k * NLB + n], s);
    out[idx] = s;
}

// ---------------- CRF ----------------
__global__ void __launch_bounds__(128) crf_kernel(
    const float* __restrict__ logits, const int* __restrict__ labels,
    const int* __restrict__ amask, const float* __restrict__ startv,
    const float* __restrict__ endv, const float* __restrict__ trans,
    float* __restrict__ llh, float* __restrict__ dout)
{
    __shared__ float em[511 * NLB];
    __shared__ float tr[NLB * NLB];
    __shared__ unsigned char bp[510 * NLB];
    __shared__ float mk[511];
    __shared__ int   tg[511];
    __shared__ float sd[NLB], sv[NLB];

    int b = blockIdx.x, tid = threadIdx.x;
    const float* lp = logits + (size_t)(b * NT + 1) * NLB;
    for (int i = tid; i < 511 * NLB; i += blockDim.x) em[i] = lp[i];
    for (int i = tid; i < NLB * NLB; i += blockDim.x) tr[i] = trans[i];
    for (int i = tid; i < 511; i += blockDim.x) {
        mk[i] = (float)amask[b * NT + 1 + i];
        tg[i] = labels[b * NT + 1 + i];
    }
    __syncthreads();

    if (tid < 32) {
        int j = tid;
        float tc[NLB];
        if (j < NLB) {
            #pragma unroll
            for (int i = 0; i < NLB; i++) tc[i] = tr[i * NLB + j];
            sd[j] = startv[j] + em[j];
            sv[j] = sd[j];
        }
        __syncwarp();
        float num = 0.f; int prev = 0;
        if (j == 0) { prev = tg[0]; num = startv[prev] + em[prev]; }

        for (int s = 1; s < 511; s++) {
            float m = mk[s];
            float nd = 0.f, nv = 0.f; int bi = 0;
            if (j < NLB) {
                float e = em[s * NLB + j];
                float mx = -1e30f;
                #pragma unroll
                for (int i = 0; i < NLB; i++) { float v = sd[i] + tc[i]; mx = fmaxf(mx, v); }
                float sum = 0.f;
                #pragma unroll
                for (int i = 0; i < NLB; i++) sum += __expf(sd[i] + tc[i] - mx);
                nd = mx + __logf(sum) + e;
                float bv = -1e30f;
                #pragma unroll
                for (int i = 0; i < NLB; i++) {
                    float v = sv[i] + tc[i];
                    if (v > bv) { bv = v; bi = i; }
                }
                bp[(s - 1) * NLB + j] = (unsigned char)bi;
                nv = bv + e;
            }
            __syncwarp();
            if (j < NLB && m > 0.f) { sd[j] = nd; sv[j] = nv; }
            if (j == 0) {
                int t = tg[s];
                num += m * (tr[prev * NLB + t] + em[s * NLB + t]);
                if (m > 0.f) prev = t;
            }
            __syncwarp();
        }

        if (j == 0) {
            num += endv[prev];
            float mx = -1e30f;
            #pragma unroll
            for (int i = 0; i < NLB; i++) mx = fmaxf(mx, sd[i] + endv[i]);
            float sum = 0.f;
            #pragma unroll
            for (int i = 0; i < NLB; i++) sum += __expf(sd[i] + endv[i] - mx);
            float den = mx + __logf(sum);
            llh[b] = num - den;

            float bv = -1e30f; int last = 0;
            #pragma unroll
            for (int i = 0; i < NLB; i++) {
                float v = sv[i] + endv[i];
                if (v > bv) { bv = v; last = i; }
            }
            float* pd = dout + 1 + (size_t)b * 511;
            pd[510] = (float)last;
            for (int s = 509; s >= 0; s--) {
                last = bp[s * NLB + last];
                pd[s] = (float)last;
            }
        }
    }
}

__global__ void loss_kernel(const float* __restrict__ llh, float* __restrict__ dout)
{
    if (threadIdx.x == 0) {
        float s = 0.f;
        for (int i = 0; i < NB; i++) s += llh[i];
        dout[0] = -s / (float)NB;
    }
}

// ---------------- launcher ----------------
extern "C" void kernel_launch(void* const* d_in, const int* in_sizes, int n_in,
                              void* d_out, int out_size)
{
    (void)in_sizes; (void)n_in; (void)out_size;
    const int*   ids  = (const int*)d_in[0];
    const int*   am   = (const int*)d_in[1];
    const int*   tti  = (const int*)d_in[2];
    const int*   lab  = (const int*)d_in[3];
    const float* we   = (const float*)d_in[4];
    const float* pe   = (const float*)d_in[5];
    const float* te   = (const float*)d_in[6];
    const float* elns = (const float*)d_in[7];
    const float* elnb = (const float*)d_in[8];
    const float* Wqkv = (const float*)d_in[9];
    const float* bqkv = (const float*)d_in[10];
    const float* Wo   = (const float*)d_in[11];
    const float* bo   = (const float*)d_in[12];
    const float* l1s  = (const float*)d_in[13];
    const float* l1b  = (const float*)d_in[14];
    const float* W1   = (const float*)d_in[15];
    const float* b1   = (const float*)d_in[16];
    const float* W2   = (const float*)d_in[17];
    const float* b2   = (const float*)d_in[18];
    const float* l2s  = (const float*)d_in[19];
    const float* l2b  = (const float*)d_in[20];
    const float* Wcls = (const float*)d_in[21];
    const float* bcls = (const float*)d_in[22];
    const float* cst  = (const float*)d_in[23];
    const float* cen  = (const float*)d_in[24];
    const float* ctr  = (const float*)d_in[25];
    float* out = (float*)d_out;

    float *x, *y, *lg, *llh;
    __half *xh, *xl, *qkvh, *qkvl, *ctxh, *ctxl, *ffh, *ffl;
    __half *wqh, *wql, *woh, *wol, *w1h, *w1l, *w2h, *w2l;
    cudaGetSymbolAddress((void**)&x,   g_x);
    cudaGetSymbolAddress((void**)&y,   g_y);
    cudaGetSymbolAddress((void**)&lg,  g_logits);
    cudaGetSymbolAddress((void**)&llh, g_llh);
    cudaGetSymbolAddress((void**)&xh,   g_xh);   cudaGetSymbolAddress((void**)&xl,   g_xl);
    cudaGetSymbolAddress((void**)&qkvh, g_qkvh); cudaGetSymbolAddress((void**)&qkvl, g_qkvl);
    cudaGetSymbolAddress((void**)&ctxh, g_ctxh); cudaGetSymbolAddress((void**)&ctxl, g_ctxl);
    cudaGetSymbolAddress((void**)&ffh,  g_ffh);  cudaGetSymbolAddress((void**)&ffl,  g_ffl);
    cudaGetSymbolAddress((void**)&wqh,  g_wqh);  cudaGetSymbolAddress((void**)&wql,  g_wql);
    cudaGetSymbolAddress((void**)&woh,  g_woh);  cudaGetSymbolAddress((void**)&wol,  g_wol);
    cudaGetSymbolAddress((void**)&w1h,  g_w1h);  cudaGetSymbolAddress((void**)&w1l,  g_w1l);
    cudaGetSymbolAddress((void**)&w2h,  g_w2h);  cudaGetSymbolAddress((void**)&w2l,  g_w2l);

    cudaFuncSetAttribute(attn_fused, cudaFuncAttributeMaxDynamicSharedMemorySize, ATTN_SMEM);

    // weight splits (once per launch)
    {
        int n;
        n = NLAY * HD * T3;  split_kernel<<<(n / 4 + 255) / 256, 256>>>(Wqkv, wqh, wql, n);
        n = NLAY * HD * HD;  split_kernel<<<(n / 4 + 255) / 256, 256>>>(Wo,   woh, wol, n);
        n = NLAY * HD * DFF; split_kernel<<<(n / 4 + 255) / 256, 256>>>(W1,   w1h, w1l, n);
        n = NLAY * DFF * HD; split_kernel<<<(n / 4 + 255) / 256, 256>>>(W2,   w2h, w2l, n);
    }

    embed_ln_kernel<<<TOK, 256>>>(ids, tti, we, pe, te, elns, elnb, x, xh, xl);

    for (int l = 0; l < NLAY; l++) {
        gemm_h<2><<<dim3(T3 / 128, TOK / 128), 256>>>(
            xh, xl, wqh + (size_t)l * HD * T3, wql + (size_t)l * HD * T3,
            bqkv + (size_t)l * T3, nullptr, qkvh, qkvl, TOK, T3, HD);
        attn_fused<<<dim3(4, NBH), 256, ATTN_SMEM>>>(qkvh, qkvl, am, ctxh, ctxl);
        gemm_h<0><<<dim3(HD / 128, TOK / 128), 256>>>(
            ctxh, ctxl, woh + (size_t)l * HD * HD, wol + (size_t)l * HD * HD,
            bo + (size_t)l * HD, y, nullptr, nullptr, TOK, HD, HD);
        ln_res_kernel<<<TOK, 256>>>(x, y, l1s + (size_t)l * HD, l1b + (size_t)l * HD, x, xh, xl);
        gemm_h<1><<<dim3(DFF / 128, TOK / 128), 256>>>(
            xh, xl, w1h + (size_t)l * HD * DFF, w1l + (size_t)l * HD * DFF,
            b1 + (size_t)l * DFF, nullptr, ffh, ffl, TOK, DFF, HD);
        gemm_h<0><<<dim3(HD / 128, TOK / 128), 256>>>(
            ffh, ffl, w2h + (size_t)l * DFF * HD, w2l + (size_t)l * DFF * HD,
            b2 + (size_t)l * HD, y, nullptr, nullptr, TOK, HD, DFF);
        ln_res_kernel<<<TOK, 256>>>(x, y, l2s + (size_t)l * HD, l2b + (size_t)l * HD, x, xh, xl);
    }

    cls_kernel<<<(TOK * NLB + 255) / 256, 256>>>(x, Wcls, bcls, lg);
    crf_kernel<<<NB, 128>>>(lg, lab, am, cst, cen, ctr, llh, out);
    loss_kernel<<<1, 32>>>(llh, out);
}

// round 15
// speedup vs baseline: 1.2896x; 1.0638x over previous
#include <cuda_runtime.h>
#include <cuda_fp16.h>
#include <math.h>
#include <stdint.h>

// ---------------- problem constants ----------------
#define NB   16
#define NT   512
#define TOK  (NB*NT)        // 8192 tokens
#define HD   768
#define T3   (3*HD)         // 2304
#define DFF  3072
#define NHH  12
#define DH   64
#define NLB  9
#define NBH  (NB*NHH)       // 192
#define NLAY 4

// ---------------- scratch (static device globals; no runtime alloc) ----------------
__device__ float g_x[TOK*HD];
__device__ float g_y[TOK*HD];
__device__ float g_logits[TOK*NLB];
__device__ float g_llh[NB];

__device__ __half g_xh[TOK*HD],   g_xl[TOK*HD];
__device__ __half g_qkvh[TOK*T3], g_qkvl[TOK*T3];
__device__ __half g_ctxh[TOK*HD], g_ctxl[TOK*HD];
__device__ __half g_ffh[TOK*DFF], g_ffl[TOK*DFF];
__device__ __half g_wqh[NLAY*HD*T3],  g_wql[NLAY*HD*T3];
__device__ __half g_woh[NLAY*HD*HD],  g_wol[NLAY*HD*HD];
__device__ __half g_w1h[NLAY*HD*DFF], g_w1l[NLAY*HD*DFF];
__device__ __half g_w2h[NLAY*DFF*HD], g_w2l[NLAY*DFF*HD];

// ---------------- helpers ----------------
__device__ __forceinline__ uint32_t s2u(const void* p) {
    uint32_t a;
    asm("{ .reg .u64 t; cvta.to.shared.u64 t, %1; cvt.u32.u64 %0, t; }" : "=r"(a) : "l"(p));
    return a;
}
__device__ __forceinline__ void splitpack(float a, float b, uint32_t& H, uint32_t& L) {
    __half2 h = __floats2half2_rn(a, b);
    float2 hf = __half22float2(h);
    __half2 l = __floats2half2_rn(a - hf.x, b - hf.y);
    H = *(uint32_t*)&h;
    L = *(uint32_t*)&l;
}
__device__ __forceinline__ void ldmx4(uint32_t* r, uint32_t addr) {
    asm volatile("ldmatrix.sync.aligned.m8n8.x4.shared.b16 {%0,%1,%2,%3}, [%4];"
        : "=r"(r[0]), "=r"(r[1]), "=r"(r[2]), "=r"(r[3]) : "r"(addr));
}
__device__ __forceinline__ void ldmx2(uint32_t* r, uint32_t addr) {
    asm volatile("ldmatrix.sync.aligned.m8n8.x2.shared.b16 {%0,%1}, [%2];"
        : "=r"(r[0]), "=r"(r[1]) : "r"(addr));
}
__device__ __forceinline__ void ldmx2t(uint32_t* r, uint32_t addr) {
    asm volatile("ldmatrix.sync.aligned.m8n8.x2.trans.shared.b16 {%0,%1}, [%2];"
        : "=r"(r[0]), "=r"(r[1]) : "r"(addr));
}
__device__ __forceinline__ void mma16816(float* c, const uint32_t* a, const uint32_t* b) {
    asm volatile(
        "mma.sync.aligned.m16n8k16.row.col.f32.f16.f16.f32 "
        "{%0,%1,%2,%3}, {%4,%5,%6,%7}, {%8,%9}, {%0,%1,%2,%3};"
        : "+f"(c[0]), "+f"(c[1]), "+f"(c[2]), "+f"(c[3])
        : "r"(a[0]), "r"(a[1]), "r"(a[2]), "r"(a[3]), "r"(b[0]), "r"(b[1]));
}
__device__ __forceinline__ float gelu_tanh(float v) {
    float u = 0.7978845608028654f * (v + 0.044715f * v * v * v);
    return 0.5f * v * (1.f + tanhf(u));
}
#define CPA16(d, s) asm volatile("cp.async.cg.shared.global [%0], [%1], 16;" :: "r"(d), "l"(s))
#define CPA_COMMIT() asm volatile("cp.async.commit_group;")

// ---------------- fp32 -> split half (weights) ----------------
__global__ void __launch_bounds__(256) split_kernel(
    const float* __restrict__ s, __half* __restrict__ h, __half* __restrict__ l, int n)
{
    int i = (blockIdx.x * blockDim.x + threadIdx.x) * 4;
    if (i >= n) return;
    float4 v = *(const float4*)(s + i);
    uint32_t H0, L0, H1, L1;
    splitpack(v.x, v.y, H0, L0);
    splitpack(v.z, v.w, H1, L1);
    *(uint32_t*)(h + i) = H0; *(uint32_t*)(h + i + 2) = H1;
    *(uint32_t*)(l + i) = L0; *(uint32_t*)(l + i + 2) = L1;
}

// ================= 3xFP16 GEMM, 3-stage cp.async pipeline =================
// C = A @ B + bias.  EPI: 0 -> fp32 C; 1 -> half CH/CL + gelu; 2 -> half CH/CL.
// Stage (bytes): AH 0 (128x40h=10240), AL 10240, BH 20480 (32x136h=8704), BL 29184. Stride 37888.
#define G_STAGE 37888
#define GEMM_SMEM (3*G_STAGE)
template<int EPI>
__global__ void __launch_bounds__(256) gemm_h(
    const __half* __restrict__ AH, const __half* __restrict__ AL,
    const __half* __restrict__ BH, const __half* __restrict__ BL,
    const float* __restrict__ bias,
    float* __restrict__ Cf, __half* __restrict__ CH, __half* __restrict__ CL,
    int M, int N, int K)
{
    extern __shared__ char smem[];
    uint32_t sb = s2u(smem);

    const int tid = threadIdx.x, warp = tid >> 5, lane = tid & 31;
    const int m0 = blockIdx.y * 128, n0 = blockIdx.x * 128;
    const int wm = (warp >> 2) * 64, wn = (warp & 3) * 32;
    const int g = lane >> 2, tg = lane & 3;

    const int am = tid >> 1, ac = (tid & 1) * 16;
    const int bk = tid >> 3, bn = (tid & 7) * 16;
    const __half* AHp = AH + (size_t)(m0 + am) * K + ac;
    const __half* ALp = AL + (size_t)(m0 + am) * K + ac;
    const __half* BHp = BH + n0 + bn;
    const __half* BLp = BL + n0 + bn;

    const uint32_t aoff = (uint32_t)((wm + (lane & 15)) * 80 + (lane >> 4) * 16);
    const uint32_t boff = (uint32_t)(((lane & 7) + 8 * ((lane >> 3) & 1)) * 272 + wn * 2);
    const uint32_t aW = (uint32_t)(am * 80 + ac * 2);
    const uint32_t bW = (uint32_t)(bk * 272 + bn * 2);

    const int Tn = K >> 5;

    auto issue = [&](int t, uint32_t stg) {
        int k0 = t << 5;
        CPA16(stg + aW,              (const char*)(AHp + k0));
        CPA16(stg + aW + 16,         (const char*)(AHp + k0 + 8));
        CPA16(stg + 10240 + aW,      (const char*)(ALp + k0));
        CPA16(stg + 10240 + aW + 16, (const char*)(ALp + k0 + 8));
        CPA16(stg + 20480 + bW,      (const char*)(BHp + (size_t)(k0 + bk) * N));
        CPA16(stg + 20480 + bW + 16, (const char*)(BHp + (size_t)(k0 + bk) * N + 8));
        CPA16(stg + 29184 + bW,      (const char*)(BLp + (size_t)(k0 + bk) * N));
        CPA16(stg + 29184 + bW + 16, (const char*)(BLp + (size_t)(k0 + bk) * N + 8));
        CPA_COMMIT();
    };

    issue(0, sb);
    issue(1, sb + G_STAGE);   // Tn >= 24 always

    float acc[16][4];
    #pragma unroll
    for (int i = 0; i < 16; i++) { acc[i][0] = acc[i][1] = acc[i][2] = acc[i][3] = 0.f; }

    int cs = 0, is = 2;
    for (int t = 0; t < Tn; t++) {
        if (t + 1 < Tn) asm volatile("cp.async.wait_group 1;");
        else            asm volatile("cp.async.wait_group 0;");
        __syncthreads();
        if (t + 2 < Tn) {
            issue(t + 2, sb + (uint32_t)is * G_STAGE);
            is = (is == 2) ? 0 : is + 1;
        }
        const uint32_t base = sb + (uint32_t)cs * G_STAGE;
        cs = (cs == 2) ? 0 : cs + 1;
        const uint32_t aHb = base, aLb = base + 10240;
        const uint32_t bHb = base + 20480, bLb = base + 29184;
        #pragma unroll
        for (int kk = 0; kk < 2; kk++) {
            uint32_t aHf[4][4], aLf[4][4], bHf[4][2], bLf[4][2];
            #pragma unroll
            for (int mf = 0; mf < 4; mf++) {
                ldmx4(aHf[mf], aHb + aoff + mf * 1280 + kk * 32);
                ldmx4(aLf[mf], aLb + aoff + mf * 1280 + kk * 32);
            }
            #pragma unroll
            for (int nf = 0; nf < 4; nf++) {
                ldmx2t(bHf[nf], bHb + boff + nf * 16 + kk * 4352);
                ldmx2t(bLf[nf], bLb + boff + nf * 16 + kk * 4352);
            }
            #pragma unroll
            for (int mf = 0; mf < 4; mf++)
                #pragma unroll
                for (int nf = 0; nf < 4; nf++) {
                    float* c = acc[mf * 4 + nf];
                    mma16816(c, aLf[mf], bHf[nf]);
                    mma16816(c, aHf[mf], bLf[nf]);
                    mma16816(c, aHf[mf], bHf[nf]);
                }
        }
    }

    #pragma unroll
    for (int mf = 0; mf < 4; mf++)
        #pragma unroll
        for (int nf = 0; nf < 4; nf++) {
            const float* c = acc[mf * 4 + nf];
            int mrow = m0 + wm + mf * 16 + g;
            int ncol = n0 + wn + nf * 8 + tg * 2;
            float b0 = bias[ncol], b1 = bias[ncol + 1];
            float v0 = c[0] + b0, v1 = c[1] + b1, v2 = c[2] + b0, v3 = c[3] + b1;
            if (EPI == 1) { v0 = gelu_tanh(v0); v1 = gelu_tanh(v1); v2 = gelu_tanh(v2); v3 = gelu_tanh(v3); }
            if (EPI == 0) {
                Cf[(size_t)mrow * N + ncol]           = v0;
                Cf[(size_t)mrow * N + ncol + 1]       = v1;
                Cf[(size_t)(mrow + 8) * N + ncol]     = v2;
                Cf[(size_t)(mrow + 8) * N + ncol + 1] = v3;
            } else {
                uint32_t H, L;
                splitpack(v0, v1, H, L);
                *(uint32_t*)&CH[(size_t)mrow * N + ncol] = H;
                *(uint32_t*)&CL[(size_t)mrow * N + ncol] = L;
                splitpack(v2, v3, H, L);
                *(uint32_t*)&CH[(size_t)(mrow + 8) * N + ncol] = H;
                *(uint32_t*)&CL[(size_t)(mrow + 8) * N + ncol] = L;
            }
        }
}

// ================= fused flash attention (3xFP16 mma, online softmax, reg prefetch) =================
// grid: (4 m-tiles, NBH). 256 threads, 8 warps x 16 query rows.
#define ATTN_SMEM (73984)
__global__ void __launch_bounds__(256, 1) attn_fused(
    const __half* __restrict__ QKVH, const __half* __restrict__ QKVL,
    const int* __restrict__ amask,
    __half* __restrict__ CTXH, __half* __restrict__ CTXL)
{
    extern __shared__ char smraw[];
    __half* QsH = (__half*)smraw;          // [128][72]
    __half* QsL = QsH + 128 * 72;
    __half* KsH = QsL + 128 * 72;          // [64][72]
    __half* KsL = KsH + 64 * 72;
    __half* VsH = KsL + 64 * 72;           // [64][72]
    __half* VsL = VsH + 64 * 72;
    float*  mkf = (float*)(VsL + 64 * 72); // [64]

    const int tid = threadIdx.x, warp = tid >> 5, lane = tid & 31;
    const int bh = blockIdx.y, b = bh / NHH, h = bh % NHH;
    const int m0 = blockIdx.x * 128;
    const int g = lane >> 2, tg = lane & 3;

    // stage Q tile (pre-split halves straight from qkv)
    {
        int am = tid >> 1, ac = (tid & 1) * 32;
        const __half* qh = QKVH + (size_t)(b * NT + m0 + am) * T3 + h * DH + ac;
        const __half* ql = QKVL + (size_t)(b * NT + m0 + am) * T3 + h * DH + ac;
        #pragma unroll
        for (int i = 0; i < 4; i++) {
            *(uint4*)&QsH[am * 72 + ac + i * 8] = *(const uint4*)(qh + i * 8);
            *(uint4*)&QsL[am * 72 + ac + i * 8] = *(const uint4*)(ql + i * 8);
        }
    }
    __syncthreads();

    uint32_t qsHb = s2u(QsH), qsLb = s2u(QsL);
    uint32_t ksHb = s2u(KsH), ksLb = s2u(KsL);
    uint32_t vsHb = s2u(VsH), vsLb = s2u(VsL);
    uint32_t qoff = (uint32_t)((warp * 16 + (lane & 15)) * 144 + (lane >> 4) * 16);
    uint32_t koff = (uint32_t)((lane & 7) * 144 + ((lane >> 3) & 1) * 16);
    uint32_t voff = (uint32_t)(((lane & 7) + 8 * ((lane >> 3) & 1)) * 144);

    uint32_t qH[4][4], qL[4][4];
    #pragma unroll
    for (int kc = 0; kc < 4; kc++) {
        ldmx4(qH[kc], qsHb + qoff + kc * 32);
        ldmx4(qL[kc], qsLb + qoff + kc * 32);
    }

    float o[8][4];
    #pragma unroll
    for (int i = 0; i < 8; i++) { o[i][0] = o[i][1] = o[i][2] = o[i][3] = 0.f; }
    float mA = -1e30f, mB = -1e30f, lA = 0.f, lB = 0.f;

    const int krow = tid >> 2, kseg = (tid & 3) * 16;
    const __half* KHp = QKVH + (size_t)(b * NT + krow) * T3 + HD + h * DH + kseg;
    const __half* KLp = QKVL + (size_t)(b * NT + krow) * T3 + HD + h * DH + kseg;
    const __half* VHp = KHp + HD;
    const __half* VLp = KLp + HD;
    const size_t kstride = (size_t)64 * T3;

    // prefetch tile 0
    uint4 rk[2], rkl[2], rv[2], rvl[2];
    int pmask = 0;
    rk[0]  = *(const uint4*)(KHp);      rk[1]  = *(const uint4*)(KHp + 8);
    rkl[0] = *(const uint4*)(KLp);      rkl[1] = *(const uint4*)(KLp + 8);
    rv[0]  = *(const uint4*)(VHp);      rv[1]  = *(const uint4*)(VHp + 8);
    rvl[0] = *(const uint4*)(VLp);      rvl[1] = *(const uint4*)(VLp + 8);
    if (tid < 64) pmask = amask[b * NT + tid];

    for (int kt = 0; kt < 8; kt++) {
        // store prefetched tile
        *(uint4*)&KsH[krow * 72 + kseg]     = rk[0];
        *(uint4*)&KsH[krow * 72 + kseg + 8] = rk[1];
        *(uint4*)&KsL[krow * 72 + kseg]     = rkl[0];
        *(uint4*)&KsL[krow * 72 + kseg + 8] = rkl[1];
        *(uint4*)&VsH[krow * 72 + kseg]     = rv[0];
        *(uint4*)&VsH[krow * 72 + kseg + 8] = rv[1];
        *(uint4*)&VsL[krow * 72 + kseg]     = rvl[0];
        *(uint4*)&VsL[krow * 72 + kseg + 8] = rvl[1];
        if (tid < 64) mkf[tid] = (1.f - (float)pmask) * -1e9f;
        __syncthreads();

        // prefetch next tile (overlaps with mma below)
        if (kt + 1 < 8) {
            size_t off = (size_t)(kt + 1) * kstride;
            rk[0]  = *(const uint4*)(KHp + off);      rk[1]  = *(const uint4*)(KHp + off + 8);
            rkl[0] = *(const uint4*)(KLp + off);      rkl[1] = *(const uint4*)(KLp + off + 8);
            rv[0]  = *(const uint4*)(VHp + off);      rv[1]  = *(const uint4*)(VHp + off + 8);
            rvl[0] = *(const uint4*)(VLp + off);      rvl[1] = *(const uint4*)(VLp + off + 8);
            if (tid < 64) pmask = amask[b * NT + (kt + 1) * 64 + tid];
        }

        // S = Q @ K^T for this 16x64 warp tile
        float s[8][4];
        #pragma unroll
        for (int i = 0; i < 8; i++) { s[i][0] = s[i][1] = s[i][2] = s[i][3] = 0.f; }
        #pragma unroll
        for (int nf = 0; nf < 8; nf++) {
            #pragma unroll
            for (int kc = 0; kc < 4; kc++) {
                uint32_t bH[2], bL[2];
                ldmx2(bH, ksHb + koff + nf * 1152 + kc * 32);
                ldmx2(bL, ksLb + koff + nf * 1152 + kc * 32);
                mma16816(s[nf], qL[kc], bH);
                mma16816(s[nf], qH[kc], bL);
                mma16816(s[nf], qH[kc], bH);
            }
        }

        // scale + mask, row max
        float rmA = -1e30f, rmB = -1e30f;
        #pragma unroll
        for (int nf = 0; nf < 8; nf++) {
            float d0 = mkf[nf * 8 + tg * 2], d1 = mkf[nf * 8 + tg * 2 + 1];
            s[nf][0] = s[nf][0] * 0.125f + d0;
            s[nf][1] = s[nf][1] * 0.125f + d1;
            s[nf][2] = s[nf][2] * 0.125f + d0;
            s[nf][3] = s[nf][3] * 0.125f + d1;
            rmA = fmaxf(rmA, fmaxf(s[nf][0], s[nf][1]));
            rmB = fmaxf(rmB, fmaxf(s[nf][2], s[nf][3]));
        }
        rmA = fmaxf(rmA, __shfl_xor_sync(0xffffffffu, rmA, 1));
        rmA = fmaxf(rmA, __shfl_xor_sync(0xffffffffu, rmA, 2));
        rmB = fmaxf(rmB, __shfl_xor_sync(0xffffffffu, rmB, 1));
        rmB = fmaxf(rmB, __shfl_xor_sync(0xffffffffu, rmB, 2));

        float nmA = fmaxf(mA, rmA), nmB = fmaxf(mB, rmB);
        float cA = __expf(mA - nmA), cB = __expf(mB - nmB);
        float rsA = 0.f, rsB = 0.f;
        #pragma unroll
        for (int nf = 0; nf < 8; nf++) {
            s[nf][0] = __expf(s[nf][0] - nmA);
            s[nf][1] = __expf(s[nf][1] - nmA);
            s[nf][2] = __expf(s[nf][2] - nmB);
            s[nf][3] = __expf(s[nf][3] - nmB);
            rsA += s[nf][0] + s[nf][1];
            rsB += s[nf][2] + s[nf][3];
        }
        rsA += __shfl_xor_sync(0xffffffffu, rsA, 1);
        rsA += __shfl_xor_sync(0xffffffffu, rsA, 2);
        rsB += __shfl_xor_sync(0xffffffffu, rsB, 1);
        rsB += __shfl_xor_sync(0xffffffffu, rsB, 2);
        lA = lA * cA + rsA;
        lB = lB * cB + rsB;
        mA = nmA; mB = nmB;
        #pragma unroll
        for (int i = 0; i < 8; i++) {
            o[i][0] *= cA; o[i][1] *= cA;
            o[i][2] *= cB; o[i][3] *= cB;
        }

        // O += P @ V   (P from S fragments directly, split hi/lo)
        #pragma unroll
        for (int kc = 0; kc < 4; kc++) {
            uint32_t pH[4], pL[4];
            splitpack(s[2 * kc][0],     s[2 * kc][1],     pH[0], pL[0]);
            splitpack(s[2 * kc][2],     s[2 * kc][3],     pH[1], pL[1]);
            splitpack(s[2 * kc + 1][0], s[2 * kc + 1][1], pH[2], pL[2]);
            splitpack(s[2 * kc + 1][2], s[2 * kc + 1][3], pH[3], pL[3]);
            #pragma unroll
            for (int nf = 0; nf < 8; nf++) {
                uint32_t vH[2], vL[2];
                ldmx2t(vH, vsHb + voff + nf * 16 + kc * 2304);
                ldmx2t(vL, vsLb + voff + nf * 16 + kc * 2304);
                mma16816(o[nf], pL, vH);
                mma16816(o[nf], pH, vL);
                mma16816(o[nf], pH, vH);
            }
        }
        __syncthreads();   // tile fully consumed before next store
    }

    // epilogue: O / l, split to halves
    float iA = 1.f / lA, iB = 1.f / lB;
    int rowA = b * NT + m0 + warp * 16 + g;
    #pragma unroll
    for (int nf = 0; nf < 8; nf++) {
        int ncol = h * DH + nf * 8 + tg * 2;
        uint32_t H, L;
        splitpack(o[nf][0] * iA, o[nf][1] * iA, H, L);
        *(uint32_t*)&CTXH[(size_t)rowA * HD + ncol] = H;
        *(uint32_t*)&CTXL[(size_t)rowA * HD + ncol] = L;
        splitpack(o[nf][2] * iB, o[nf][3] * iB, H, L);
        *(uint32_t*)&CTXH[(size_t)(rowA + 8) * HD + ncol] = H;
        *(uint32_t*)&CTXL[(size_t)(rowA + 8) * HD + ncol] = L;
    }
}

// ---------------- reductions ----------------
__device__ __forceinline__ void reduce2_256(float& a, float& b) {
    __shared__ float sa[8], sb[8];
    #pragma unroll
    for (int o = 16; o; o >>= 1) {
        a += __shfl_xor_sync(0xffffffffu, a, o);
        b += __shfl_xor_sync(0xffffffffu, b, o);
    }
    int w = threadIdx.x >> 5;
    if ((threadIdx.x & 31) == 0) { sa[w] = a; sb[w] = b; }
    __syncthreads();
    a = 0.f; b = 0.f;
    #pragma unroll
    for (int i = 0; i < 8; i++) { a += sa[i]; b += sb[i]; }
}

// ---------------- embedding + LN ----------------
__global__ void __launch_bounds__(256) embed_ln_kernel(
    const int* __restrict__ ids, const int* __restrict__ tt,
    const float* __restrict__ we, const float* __restrict__ pe, const float* __restrict__ te,
    const float* __restrict__ sc, const float* __restrict__ bi,
    float* __restrict__ x, __half* __restrict__ xh, __half* __restrict__ xl)
{
    int tok = blockIdx.x;
    int t   = tok & (NT - 1);
    int tid = threadIdx.x;
    const float* w  = we + (size_t)ids[tok] * HD;
    const float* p  = pe + (size_t)t * HD;
    const float* ty = te + (size_t)tt[tok] * HD;
    float e[3]; float sum = 0.f, sq = 0.f;
    #pragma unroll
    for (int i = 0; i < 3; i++) {
        int c = tid + i * 256;
        float v = w[c] + p[c] + ty[c];
        e[i] = v; sum += v; sq += v * v;
    }
    reduce2_256(sum, sq);
    float mean = sum * (1.f / HD);
    float var  = sq * (1.f / HD) - mean * mean;
    float inv  = rsqrtf(var + 1e-12f);
    #pragma unroll
    for (int i = 0; i < 3; i++) {
        int c = tid + i * 256;
        float v = (e[i] - mean) * inv * sc[c] + bi[c];
        size_t idx = (size_t)tok * HD + c;
        x[idx] = v;
        __half h = __float2half_rn(v);
        xh[idx] = h;
        xl[idx] = __float2half_rn(v - __half2float(h));
    }
}

// ---------------- residual + LN ----------------
__global__ void __launch_bounds__(256) ln_res_kernel(
    const float* __restrict__ xin, const float* __restrict__ y,
    const float* __restrict__ sc, const float* __restrict__ bi,
    float* __restrict__ xout, __half* __restrict__ xh, __half* __restrict__ xl)
{
    int tok = blockIdx.x;
    int tid = threadIdx.x;
    float e[3]; float sum = 0.f, sq = 0.f;
    #pragma unroll
    for (int i = 0; i < 3; i++) {
        int c = tid + i * 256;
        float v = xin[(size_t)tok * HD + c] + y[(size_t)tok * HD + c];
        e[i] = v; sum += v; sq += v * v;
    }
    reduce2_256(sum, sq);
    float mean = sum * (1.f / HD);
    float var  = sq * (1.f / HD) - mean * mean;
    float inv  = rsqrtf(var + 1e-12f);
    #pragma unroll
    for (int i = 0; i < 3; i++) {
        int c = tid + i * 256;
        float v = (e[i] - mean) * inv * sc[c] + bi[c];
        size_t idx = (size_t)tok * HD + c;
        xout[idx] = v;
        __half h = __float2half_rn(v);
        xh[idx] = h;
        xl[idx] = __float2half_rn(v - __half2float(h));
    }
}

// ---------------- classifier ----------------
__global__ void __launch_bounds__(256) cls_kernel(
    const float* __restrict__ x, const float* __restrict__ W,
    const float* __restrict__ bias, float* __restrict__ out)
{
    int idx = blockIdx.x * blockDim.x + threadIdx.x;
    if (idx >= TOK * NLB) return;
    int tok = idx / NLB, n = idx % NLB;
    const float* xr = x + (size_t)tok * HD;
    float s = bias[n];
    #pragma unroll 8
    for (int k = 0; k < HD; k++) s = fmaf(xr[k], W[k * NLB + n], s);
    out[idx] = s;
}

// ---------------- CRF ----------------
__global__ void __launch_bounds__(128) crf_kernel(
    const float* __restrict__ logits, const int* __restrict__ labels,
    const int* __restrict__ amask, const float* __restrict__ startv,
    const float* __restrict__ endv, const float* __restrict__ trans,
    float* __restrict__ llh, float* __restrict__ dout)
{
    __shared__ float em[511 * NLB];
    __shared__ float tr[NLB * NLB];
    __shared__ unsigned char bp[510 * NLB];
    __shared__ float mk[511];
    __shared__ int   tg[511];
    __shared__ float sd[NLB], sv[NLB];

    int b = blockIdx.x, tid = threadIdx.x;
    const float* lp = logits + (size_t)(b * NT + 1) * NLB;
    for (int i = tid; i < 511 * NLB; i += blockDim.x) em[i] = lp[i];
    for (int i = tid; i < NLB * NLB; i += blockDim.x) tr[i] = trans[i];
    for (int i = tid; i < 511; i += blockDim.x) {
        mk[i] = (float)amask[b * NT + 1 + i];
        tg[i] = labels[b * NT + 1 + i];
    }
    __syncthreads();

    if (tid < 32) {
        int j = tid;
        float tc[NLB];
        if (j < NLB) {
            #pragma unroll
            for (int i = 0; i < NLB; i++) tc[i] = tr[i * NLB + j];
            sd[j] = startv[j] + em[j];
            sv[j] = sd[j];
        }
        __syncwarp();
        float num = 0.f; int prev = 0;
        if (j == 0) { prev = tg[0]; num = startv[prev] + em[prev]; }

        for (int s = 1; s < 511; s++) {
            float m = mk[s];
            float nd = 0.f, nv = 0.f; int bi = 0;
            if (j < NLB) {
                float e = em[s * NLB + j];
                float mx = -1e30f;
                #pragma unroll
                for (int i = 0; i < NLB; i++) { float v = sd[i] + tc[i]; mx = fmaxf(mx, v); }
                float sum = 0.f;
                #pragma unroll
                for (int i = 0; i < NLB; i++) sum += __expf(sd[i] + tc[i] - mx);
                nd = mx + __logf(sum) + e;
                float bv = -1e30f;
                #pragma unroll
                for (int i = 0; i < NLB; i++) {
                    float v = sv[i] + tc[i];
                    if (v > bv) { bv = v; bi = i; }
                }
                bp[(s - 1) * NLB + j] = (unsigned char)bi;
                nv = bv + e;
            }
            __syncwarp();
            if (j < NLB && m > 0.f) { sd[j] = nd; sv[j] = nv; }
            if (j == 0) {
                int t = tg[s];
                num += m * (tr[prev * NLB + t] + em[s * NLB + t]);
                if (m > 0.f) prev = t;
            }
            __syncwarp();
        }

        if (j == 0) {
            num += endv[prev];
            float mx = -1e30f;
            #pragma unroll
            for (int i = 0; i < NLB; i++) mx = fmaxf(mx, sd[i] + endv[i]);
            float sum = 0.f;
            #pragma unroll
            for (int i = 0; i < NLB; i++) sum += __expf(sd[i] + endv[i] - mx);
            float den = mx + __logf(sum);
            llh[b] = num - den;

            float bv = -1e30f; int last = 0;
            #pragma unroll
            for (int i = 0; i < NLB; i++) {
                float v = sv[i] + endv[i];
                if (v > bv) { bv = v; last = i; }
            }
            float* pd = dout + 1 + (size_t)b * 511;
            pd[510] = (float)last;
            for (int s = 509; s >= 0; s--) {
                last = bp[s * NLB + last];
                pd[s] = (float)last;
            }
        }
    }
}

__global__ void loss_kernel(const float* __restrict__ llh, float* __restrict__ dout)
{
    if (threadIdx.x == 0) {
        float s = 0.f;
        for (int i = 0; i < NB; i++) s += llh[i];
        dout[0] = -s / (float)NB;
    }
}

// ---------------- launcher ----------------
extern "C" void kernel_launch(void* const* d_in, const int* in_sizes, int n_in,
                              void* d_out, int out_size)
{
    (void)in_sizes; (void)n_in; (void)out_size;
    const int*   ids  = (const int*)d_in[0];
    const int*   am   = (const int*)d_in[1];
    const int*   tti  = (const int*)d_in[2];
    const int*   lab  = (const int*)d_in[3];
    const float* we   = (const float*)d_in[4];
    const float* pe   = (const float*)d_in[5];
    const float* te   = (const float*)d_in[6];
    const float* elns = (const float*)d_in[7];
    const float* elnb = (const float*)d_in[8];
    const float* Wqkv = (const float*)d_in[9];
    const float* bqkv = (const float*)d_in[10];
    const float* Wo   = (const float*)d_in[11];
    const float* bo   = (const float*)d_in[12];
    const float* l1s  = (const float*)d_in[13];
    const float* l1b  = (const float*)d_in[14];
    const float* W1   = (const float*)d_in[15];
    const float* b1   = (const float*)d_in[16];
    const float* W2   = (const float*)d_in[17];
    const float* b2   = (const float*)d_in[18];
    const float* l2s  = (const float*)d_in[19];
    const float* l2b  = (const float*)d_in[20];
    const float* Wcls = (const float*)d_in[21];
    const float* bcls = (const float*)d_in[22];
    const float* cst  = (const float*)d_in[23];
    const float* cen  = (const float*)d_in[24];
    const float* ctr  = (const float*)d_in[25];
    float* out = (float*)d_out;

    float *x, *y, *lg, *llh;
    __half *xh, *xl, *qkvh, *qkvl, *ctxh, *ctxl, *ffh, *ffl;
    __half *wqh, *wql, *woh, *wol, *w1h, *w1l, *w2h, *w2l;
    cudaGetSymbolAddress((void**)&x,   g_x);
    cudaGetSymbolAddress((void**)&y,   g_y);
    cudaGetSymbolAddress((void**)&lg,  g_logits);
    cudaGetSymbolAddress((void**)&llh, g_llh);
    cudaGetSymbolAddress((void**)&xh,   g_xh);   cudaGetSymbolAddress((void**)&xl,   g_xl);
    cudaGetSymbolAddress((void**)&qkvh, g_qkvh); cudaGetSymbolAddress((void**)&qkvl, g_qkvl);
    cudaGetSymbolAddress((void**)&ctxh, g_ctxh); cudaGetSymbolAddress((void**)&ctxl, g_ctxl);
    cudaGetSymbolAddress((void**)&ffh,  g_ffh);  cudaGetSymbolAddress((void**)&ffl,  g_ffl);
    cudaGetSymbolAddress((void**)&wqh,  g_wqh);  cudaGetSymbolAddress((void**)&wql,  g_wql);
    cudaGetSymbolAddress((void**)&woh,  g_woh);  cudaGetSymbolAddress((void**)&wol,  g_wol);
    cudaGetSymbolAddress((void**)&w1h,  g_w1h);  cudaGetSymbolAddress((void**)&w1l,  g_w1l);
    cudaGetSymbolAddress((void**)&w2h,  g_w2h);  cudaGetSymbolAddress((void**)&w2l,  g_w2l);

    cudaFuncSetAttribute(attn_fused, cudaFuncAttributeMaxDynamicSharedMemorySize, ATTN_SMEM);
    cudaFuncSetAttribute(gemm_h<0>, cudaFuncAttributeMaxDynamicSharedMemorySize, GEMM_SMEM);
    cudaFuncSetAttribute(gemm_h<1>, cudaFuncAttributeMaxDynamicSharedMemorySize, GEMM_SMEM);
    cudaFuncSetAttribute(gemm_h<2>, cudaFuncAttributeMaxDynamicSharedMemorySize, GEMM_SMEM);

    // weight splits (once per launch)
    {
        int n;
        n = NLAY * HD * T3;  split_kernel<<<(n / 4 + 255) / 256, 256>>>(Wqkv, wqh, wql, n);
        n = NLAY * HD * HD;  split_kernel<<<(n / 4 + 255) / 256, 256>>>(Wo,   woh, wol, n);
        n = NLAY * HD * DFF; split_kernel<<<(n / 4 + 255) / 256, 256>>>(W1,   w1h, w1l, n);
        n = NLAY * DFF * HD; split_kernel<<<(n / 4 + 255) / 256, 256>>>(W2,   w2h, w2l, n);
    }

    embed_ln_kernel<<<TOK, 256>>>(ids, tti, we, pe, te, elns, elnb, x, xh, xl);

    for (int l = 0; l < NLAY; l++) {
        gemm_h<2><<<dim3(T3 / 128, TOK / 128), 256, GEMM_SMEM>>>(
            xh, xl, wqh + (size_t)l * HD * T3, wql + (size_t)l * HD * T3,
            bqkv + (size_t)l * T3, nullptr, qkvh, qkvl, TOK, T3, HD);
        attn_fused<<<dim3(4, NBH), 256, ATTN_SMEM>>>(qkvh, qkvl, am, ctxh, ctxl);
        gemm_h<0><<<dim3(HD / 128, TOK / 128), 256, GEMM_SMEM>>>(
            ctxh, ctxl, woh + (size_t)l * HD * HD, wol + (size_t)l * HD * HD,
            bo + (size_t)l * HD, y, nullptr, nullptr, TOK, HD, HD);
        ln_res_kernel<<<TOK, 256>>>(x, y, l1s + (size_t)l * HD, l1b + (size_t)l * HD, x, xh, xl);
        gemm_h<1><<<dim3(DFF / 128, TOK / 128), 256, GEMM_SMEM>>>(
            xh, xl, w1h + (size_t)l * HD * DFF, w1l + (size_t)l * HD * DFF,
            b1 + (size_t)l * DFF, nullptr, ffh, ffl, TOK, DFF, HD);
        gemm_h<0><<<dim3(HD / 128, TOK / 128), 256, GEMM_SMEM>>>(
            ffh, ffl, w2h + (size_t)l * DFF * HD, w2l + (size_t)l * DFF * HD,
            b2 + (size_t)l * HD, y, nullptr, nullptr, TOK, HD, DFF);
        ln_res_kernel<<<TOK, 256>>>(x, y, l2s + (size_t)l * HD, l2b + (size_t)l * HD, x, xh, xl);
    }

    cls_kernel<<<(TOK * NLB + 255) / 256, 256>>>(x, Wcls, bcls, lg);
    crf_kernel<<<NB, 128>>>(lg, lab, am, cst, cen, ctr, llh, out);
    loss_kernel<<<1, 32>>>(llh, out);
}